// round 8
// baseline (speedup 1.0000x reference)
#include <cuda_runtime.h>

#define NN 50000
#define EE 800000
#define NEG 0.2f

typedef unsigned long long u64;

// ---------------- scratch (static device globals; no allocation) ----------------
__device__ __align__(16) float    g_gl1[NN * 128];
__device__ __align__(16) float    g_gr1[NN * 128];
__device__ __align__(16) float    g_h1 [NN * 128];
__device__ __align__(16) float    g_gl2[NN * 32];
__device__ __align__(16) float    g_gr2[NN * 32];
// CSR by dst
__device__ unsigned g_cnt[NN];
__device__ unsigned g_rowstart[NN];
__device__ unsigned g_cursor[NN];
__device__ int      g_csrc[EE];

// ---------------- f32x2 helpers ----------------
__device__ __forceinline__ u64 pack2(float lo, float hi) {
    u64 r;
    asm("mov.b64 %0, {%1, %2};" : "=l"(r) : "f"(lo), "f"(hi));
    return r;
}
__device__ __forceinline__ float2 unpack2(u64 v) {
    float2 r;
    asm("mov.b64 {%0, %1}, %2;" : "=f"(r.x), "=f"(r.y) : "l"(v));
    return r;
}
__device__ __forceinline__ void ffma2(u64& d, u64 a, u64 b) {
    asm("fma.rn.f32x2 %0, %1, %2, %0;" : "+l"(d) : "l"(a), "l"(b));
}

// ---------------- CSR build ----------------
__global__ void csr_init_kernel() {
    int i = blockIdx.x * blockDim.x + threadIdx.x;
    if (i < NN) g_cnt[i] = 0u;
}
__global__ void csr_hist_kernel(const int* __restrict__ ei) {
    int i = blockIdx.x * blockDim.x + threadIdx.x;
    if (i < EE) atomicAdd(&g_cnt[ei[EE + i]], 1u);
}
__global__ __launch_bounds__(1024) void csr_scan_kernel() {
    __shared__ unsigned s[1024];
    const int T = 1024;
    const int CH = (NN + T - 1) / T;
    int t = threadIdx.x;
    int base = t * CH;
    unsigned sum = 0;
    for (int i = 0; i < CH; i++) {
        int j = base + i;
        if (j < NN) sum += g_cnt[j];
    }
    s[t] = sum;
    __syncthreads();
    for (int off = 1; off < T; off <<= 1) {
        unsigned u = (t >= off) ? s[t - off] : 0u;
        __syncthreads();
        s[t] += u;
        __syncthreads();
    }
    unsigned run = s[t] - sum;
    for (int i = 0; i < CH; i++) {
        int j = base + i;
        if (j < NN) {
            unsigned c = g_cnt[j];
            g_rowstart[j] = run;
            g_cursor[j]   = run;
            run += c;
        }
    }
}
__global__ void csr_fill_kernel(const int* __restrict__ ei) {
    int i = blockIdx.x * blockDim.x + threadIdx.x;
    if (i < EE) {
        int d = ei[EE + i];
        unsigned pos = atomicAdd(&g_cursor[d], 1u);
        g_csrc[pos] = ei[i];
    }
}

// ---------------- GEMM: conflict-free smem, f32x2, RB=64 for 3-4 blocks/SM --------
// A:[n,128] row-major; W:[128,M]. Block computes RB rows x MBLK cols of one matrix.
// grid.y = mat * (M/MBLK) + half. 256 threads; TXN=MBLK/CT; TYN=256/TXN; RT=RB/TYN.
template <int M, int MBLK, int CT, int RB>
__global__ __launch_bounds__(256) void gemm_kernel(
    const float* __restrict__ A, int n,
    const float* __restrict__ W1, const float* __restrict__ b1, float* __restrict__ C1,
    const float* __restrict__ W2, const float* __restrict__ b2, float* __restrict__ C2)
{
    constexpr int K    = 128;
    constexpr int TXN  = MBLK / CT;     // 8
    constexpr int TYN  = 256 / TXN;     // 32
    constexpr int RT   = RB / TYN;      // 2
    constexpr int CP   = CT / 2;        // u64 accs per row: 4 or 2
    constexpr int NCH  = CT / 4;        // 16B chunks per thread: 2 or 1
    constexpr int NH   = M / MBLK;      // column-halves per matrix
    constexpr int AP   = 33;            // A pitch in float4

    extern __shared__ float sm[];
    float4* As4 = reinterpret_cast<float4*>(sm);            // RB * AP float4
    float4* Ws4 = reinterpret_cast<float4*>(sm) + RB * AP;  // K * MBLK/4 swizzled

    const int mat  = blockIdx.y / NH;
    const int col0 = (blockIdx.y % NH) * MBLK;
    const float* __restrict__ W = mat ? W2 : W1;
    const float* __restrict__ b = mat ? b2 : b1;
    float* __restrict__       C = mat ? C2 : C1;

    const int tid  = threadIdx.x;
    const int row0 = blockIdx.x * RB;

    // fill A tile: coalesced read, padded-pitch write
    for (int i = tid; i < RB * 32; i += 256) {
        int r  = i >> 5;
        int c4 = i & 31;
        int gr_ = row0 + r;
        float4 v = make_float4(0.f, 0.f, 0.f, 0.f);
        if (gr_ < n) v = reinterpret_cast<const float4*>(A)[gr_ * 32 + c4];
        As4[r * AP + c4] = v;
    }
    // fill W tile swizzled: src (k, c) -> dst (k*NCH + chunk)*TXN + txg
    for (int i = tid; i < K * (MBLK / 4); i += 256) {
        int k  = i / (MBLK / 4);
        int c4 = i % (MBLK / 4);
        int c  = c4 * 4;
        int txg   = c / CT;
        int chunk = (c % CT) >> 2;
        float4 v = reinterpret_cast<const float4*>(W + k * M + col0)[c4];
        Ws4[(k * NCH + chunk) * TXN + txg] = v;
    }
    __syncthreads();

    const int tx = tid % TXN;
    const int ty = tid / TXN;

    u64 acc[RT][CP];
    const u64 zz = pack2(0.f, 0.f);
#pragma unroll
    for (int i = 0; i < RT; i++)
#pragma unroll
        for (int j = 0; j < CP; j++) acc[i][j] = zz;

#pragma unroll 2
    for (int k4 = 0; k4 < K / 4; ++k4) {
        float4 av[RT];
#pragma unroll
        for (int i = 0; i < RT; i++)
            av[i] = As4[(ty + i * TYN) * AP + k4];   // strided rows

#pragma unroll
        for (int kk = 0; kk < 4; ++kk) {
            u64 wv[CP];
            const ulonglong2* wp = reinterpret_cast<const ulonglong2*>(
                Ws4 + (k4 * 4 + kk) * NCH * TXN);
#pragma unroll
            for (int jc = 0; jc < NCH; ++jc) {
                ulonglong2 u = wp[jc * TXN + tx];    // 128B contiguous per warp
                wv[jc * 2] = u.x;
                if constexpr (CP > 1) wv[jc * 2 + 1] = u.y;
            }
#pragma unroll
            for (int i = 0; i < RT; i++) {
                float a = (kk == 0) ? av[i].x : (kk == 1) ? av[i].y
                        : (kk == 2) ? av[i].z : av[i].w;
                u64 ap = pack2(a, a);
#pragma unroll
                for (int j = 0; j < CP; j++) ffma2(acc[i][j], ap, wv[j]);
            }
        }
    }

#pragma unroll
    for (int i = 0; i < RT; i++) {
        int r = row0 + ty + i * TYN;
        if (r < n) {
#pragma unroll
            for (int j = 0; j < CP; j++) {
                int c = col0 + tx * CT + j * 2;
                float2 v = unpack2(acc[i][j]);
                C[r * M + c]     = v.x + b[c];
                C[r * M + c + 1] = v.y + b[c + 1];
            }
        }
    }
}

// ---------------- layer 1: fused attention aggregation (warp per dst) ----------------
__global__ __launch_bounds__(256) void agg1_kernel(const float* __restrict__ att,
                                                   const float* __restrict__ bias) {
    const int lane = threadIdx.x & 31;
    const int d = blockIdx.x * (blockDim.x >> 5) + (threadIdx.x >> 5);
    if (d >= NN) return;

    const float4* __restrict__ gl4 = reinterpret_cast<const float4*>(g_gl1);
    const float4  grd = reinterpret_cast<const float4*>(g_gr1)[d * 32 + lane];
    const float4  at  = reinterpret_cast<const float4*>(att)[lane];

    float4 acc = make_float4(0.f, 0.f, 0.f, 0.f);
    float  den = 0.f;

    const unsigned start = g_rowstart[d];
    const unsigned deg   = g_cnt[d];

    int s1 = (deg > 0) ? g_csrc[start]     : d;
    int s2 = (deg > 1) ? g_csrc[start + 1] : d;
    float4 gcur  = gl4[d  * 32 + lane];
    float4 gnext = gl4[s1 * 32 + lane];

    for (unsigned j = 0; j <= deg; ++j) {
        float4 gnn = gl4[s2 * 32 + lane];
        s2 = (j + 3 <= deg) ? g_csrc[start + j + 2] : d;

        float m0 = gcur.x + grd.x; m0 = (m0 > 0.f) ? m0 : NEG * m0;
        float m1 = gcur.y + grd.y; m1 = (m1 > 0.f) ? m1 : NEG * m1;
        float m2 = gcur.z + grd.z; m2 = (m2 > 0.f) ? m2 : NEG * m2;
        float m3 = gcur.w + grd.w; m3 = (m3 > 0.f) ? m3 : NEG * m3;
        float p = at.x * m0 + at.y * m1 + at.z * m2 + at.w * m3;
        p += __shfl_xor_sync(0xffffffffu, p, 1);
        p += __shfl_xor_sync(0xffffffffu, p, 2);
        p += __shfl_xor_sync(0xffffffffu, p, 4);
        float w = __expf(p);
        acc.x += w * gcur.x;
        acc.y += w * gcur.y;
        acc.z += w * gcur.z;
        acc.w += w * gcur.w;
        den += w;

        gcur = gnext;
        gnext = gnn;
    }

    const float inv = 1.f / den;
    const float4 b = reinterpret_cast<const float4*>(bias)[lane];
    float v0 = acc.x * inv + b.x; v0 = (v0 > 0.f) ? v0 : expm1f(v0);
    float v1 = acc.y * inv + b.y; v1 = (v1 > 0.f) ? v1 : expm1f(v1);
    float v2 = acc.z * inv + b.z; v2 = (v2 > 0.f) ? v2 : expm1f(v2);
    float v3 = acc.w * inv + b.w; v3 = (v3 > 0.f) ? v3 : expm1f(v3);
    reinterpret_cast<float4*>(g_h1)[d * 32 + lane] = make_float4(v0, v1, v2, v3);
}

// ---------------- layer 2: aggregation, 4 dsts per warp (8 lanes / dst) -------------
__global__ __launch_bounds__(256) void agg2_kernel(const float* __restrict__ att,
                                                   const float* __restrict__ bias,
                                                   float* __restrict__ out) {
    const int lane = threadIdx.x & 31;
    const int grp  = lane >> 3;
    const int lg   = lane & 7;
    const int wid  = blockIdx.x * (blockDim.x >> 5) + (threadIdx.x >> 5);
    int d = wid * 4 + grp;
    const bool dvalid = (d < NN);
    if (d >= NN) d = NN - 1;

    const float4* __restrict__ gl4 = reinterpret_cast<const float4*>(g_gl2);
    const float4 grd  = reinterpret_cast<const float4*>(g_gr2)[d * 8 + lg];
    const float4 at   = reinterpret_cast<const float4*>(att)[lg];

    const unsigned start = g_rowstart[d];
    const unsigned deg   = dvalid ? g_cnt[d] : 0u;

    unsigned mdeg = deg;
#pragma unroll
    for (int off = 8; off < 32; off <<= 1) {
        unsigned o = __shfl_xor_sync(0xffffffffu, mdeg, off);
        mdeg = (o > mdeg) ? o : mdeg;
    }

    float4 acc = make_float4(0.f, 0.f, 0.f, 0.f);
    float  den = 0.f;

    int snext = (deg > 0) ? g_csrc[start] : d;
    float4 g = gl4[d * 8 + lg];

    for (unsigned j = 0; j <= mdeg; ++j) {
        float4 gc = g;
        int snn = (j + 2 <= deg) ? g_csrc[start + j + 1] : d;
        g = gl4[snext * 8 + lg];
        snext = snn;

        float m0 = gc.x + grd.x; m0 = (m0 > 0.f) ? m0 : NEG * m0;
        float m1 = gc.y + grd.y; m1 = (m1 > 0.f) ? m1 : NEG * m1;
        float m2 = gc.z + grd.z; m2 = (m2 > 0.f) ? m2 : NEG * m2;
        float m3 = gc.w + grd.w; m3 = (m3 > 0.f) ? m3 : NEG * m3;
        float p = at.x * m0 + at.y * m1 + at.z * m2 + at.w * m3;
        p += __shfl_xor_sync(0xffffffffu, p, 1);
        p += __shfl_xor_sync(0xffffffffu, p, 2);
        p += __shfl_xor_sync(0xffffffffu, p, 4);
        float w = (j <= deg) ? __expf(p) : 0.f;
        acc.x += w * gc.x;
        acc.y += w * gc.y;
        acc.z += w * gc.z;
        acc.w += w * gc.w;
        den += w;
    }

    if (dvalid) {
        const float inv = 1.f / den;
        const float4 b = reinterpret_cast<const float4*>(bias)[lg];
        reinterpret_cast<float4*>(out)[d * 8 + lg] =
            make_float4(acc.x * inv + b.x, acc.y * inv + b.y,
                        acc.z * inv + b.z, acc.w * inv + b.w);
    }
}

// ---------------- side-stream resources (host-side handles; created once) ----------
struct SideStream {
    cudaStream_t s;
    cudaEvent_t  fork, join;
    SideStream() {
        cudaStreamCreateWithFlags(&s, cudaStreamNonBlocking);
        cudaEventCreateWithFlags(&fork, cudaEventDisableTiming);
        cudaEventCreateWithFlags(&join, cudaEventDisableTiming);
    }
};

// ---------------- launch ----------------
extern "C" void kernel_launch(void* const* d_in, const int* in_sizes, int n_in,
                              void* d_out, int out_size) {
    const float* x    = (const float*)d_in[0];
    const int*   ei   = (const int*)d_in[1];
    const float* Wl1  = (const float*)d_in[2];
    const float* bl1  = (const float*)d_in[3];
    const float* Wr1  = (const float*)d_in[4];
    const float* br1  = (const float*)d_in[5];
    const float* att1 = (const float*)d_in[6];
    const float* bias1= (const float*)d_in[7];
    const float* Wl2  = (const float*)d_in[8];
    const float* bl2  = (const float*)d_in[9];
    const float* Wr2  = (const float*)d_in[10];
    const float* br2  = (const float*)d_in[11];
    const float* att2 = (const float*)d_in[12];
    const float* bias2= (const float*)d_in[13];
    float* out = (float*)d_out;

    static SideStream ss;   // created once; identical launched work every call

    // gemm1: M=128, MBLK=64, CT=8, RB=64 -> smem 64*33*16 + 128*64*4 = 66560 (3/SM)
    // gemm2: M=32,  MBLK=32, CT=4, RB=64 -> smem 64*33*16 + 128*32*4 = 50176 (4/SM)
    const int smem1 = 64 * 33 * 16 + 128 * 64 * 4;
    const int smem2 = 64 * 33 * 16 + 128 * 32 * 4;
    cudaFuncSetAttribute((gemm_kernel<128, 64, 8, 64>),
                         cudaFuncAttributeMaxDynamicSharedMemorySize, smem1);
    cudaFuncSetAttribute((gemm_kernel<32, 32, 4, 64>),
                         cudaFuncAttributeMaxDynamicSharedMemorySize, smem2);

    float *gl1p, *gr1p, *h1p, *gl2p, *gr2p;
    cudaGetSymbolAddress((void**)&gl1p, g_gl1);
    cudaGetSymbolAddress((void**)&gr1p, g_gr1);
    cudaGetSymbolAddress((void**)&h1p,  g_h1);
    cudaGetSymbolAddress((void**)&gl2p, g_gl2);
    cudaGetSymbolAddress((void**)&gr2p, g_gr2);

    // fork: CSR chain on side stream, gemm1 on main stream (concurrent)
    cudaEventRecord(ss.fork, 0);
    cudaStreamWaitEvent(ss.s, ss.fork, 0);

    csr_init_kernel<<<(NN + 255) / 256, 256, 0, ss.s>>>();          // slot 1
    csr_hist_kernel<<<(EE + 255) / 256, 256, 0, ss.s>>>(ei);        // slot 2
    csr_scan_kernel<<<1, 1024, 0, ss.s>>>();                        // slot 3

    gemm_kernel<128, 64, 8, 64><<<dim3((NN + 63) / 64, 4), 256, smem1>>>(
        x, NN, Wl1, bl1, gl1p, Wr1, br1, gr1p);                     // slot 4 (profiled)

    csr_fill_kernel<<<(EE + 255) / 256, 256, 0, ss.s>>>(ei);        // slot 5

    // join: agg1 needs both gemm1 (main) and CSR (side)
    cudaEventRecord(ss.join, ss.s);
    cudaStreamWaitEvent(0, ss.join, 0);

    agg1_kernel<<<(NN + 7) / 8, 256>>>(att1, bias1);

    gemm_kernel<32, 32, 4, 64><<<dim3((NN + 63) / 64, 2), 256, smem2>>>(
        h1p, NN, Wl2, bl2, gl2p, Wr2, br2, gr2p);
    agg2_kernel<<<(NN + 31) / 32, 256>>>(att2, bias2, out);
}

// round 9
// speedup vs baseline: 1.1081x; 1.1081x over previous
#include <cuda_runtime.h>

#define NN 50000
#define EE 800000
#define NEG 0.2f

typedef unsigned long long u64;

// ---------------- scratch (static device globals; no allocation) ----------------
__device__ __align__(16) float    g_gl1[NN * 128];
__device__ __align__(16) float    g_gr1[NN * 128];
__device__ __align__(16) float    g_h1 [NN * 128];
__device__ __align__(16) float    g_gl2[NN * 32];
__device__ __align__(16) float    g_gr2[NN * 32];
// CSR by dst
__device__ unsigned g_cnt[NN];          // statically zero; scan re-zeroes each call
__device__ unsigned g_rowstart[NN + 1];
__device__ unsigned g_cursor[NN];
__device__ int      g_csrc[EE];

// ---------------- f32x2 helpers ----------------
__device__ __forceinline__ u64 pack2(float lo, float hi) {
    u64 r;
    asm("mov.b64 %0, {%1, %2};" : "=l"(r) : "f"(lo), "f"(hi));
    return r;
}
__device__ __forceinline__ float2 unpack2(u64 v) {
    float2 r;
    asm("mov.b64 {%0, %1}, %2;" : "=f"(r.x), "=f"(r.y) : "l"(v));
    return r;
}
__device__ __forceinline__ void ffma2(u64& d, u64 a, u64 b) {
    asm("fma.rn.f32x2 %0, %1, %2, %0;" : "+l"(d) : "l"(a), "l"(b));
}

// ---------------- CSR build ----------------
__global__ void csr_hist_kernel(const int* __restrict__ ei) {
    int i = blockIdx.x * blockDim.x + threadIdx.x;
    if (i < EE) atomicAdd(&g_cnt[ei[EE + i]], 1u);
}
// single-block exclusive scan; consumes AND re-zeroes g_cnt (ready for next call)
__global__ __launch_bounds__(1024) void csr_scan_kernel() {
    __shared__ unsigned s[1024];
    const int T = 1024;
    const int CH = (NN + T - 1) / T;
    int t = threadIdx.x;
    int base = t * CH;
    unsigned sum = 0;
    for (int i = 0; i < CH; i++) {
        int j = base + i;
        if (j < NN) sum += g_cnt[j];
    }
    s[t] = sum;
    __syncthreads();
    for (int off = 1; off < T; off <<= 1) {
        unsigned u = (t >= off) ? s[t - off] : 0u;
        __syncthreads();
        s[t] += u;
        __syncthreads();
    }
    unsigned run = s[t] - sum;
    for (int i = 0; i < CH; i++) {
        int j = base + i;
        if (j < NN) {
            unsigned c = g_cnt[j];
            g_cnt[j] = 0u;            // self-reset for the next graph replay
            g_rowstart[j] = run;
            g_cursor[j]   = run;
            run += c;
        }
    }
    if (t == T - 1) g_rowstart[NN] = run;   // == EE
}
__global__ void csr_fill_kernel(const int* __restrict__ ei) {
    int i = blockIdx.x * blockDim.x + threadIdx.x;
    if (i < EE) {
        int d = ei[EE + i];
        unsigned pos = atomicAdd(&g_cursor[d], 1u);
        g_csrc[pos] = ei[i];
    }
}

// ---------------- GEMM: conflict-free smem, f32x2, N-split for occupancy ----------
// A:[n,128] row-major; W:[128,M]. Block computes RB rows x MBLK cols of one matrix.
// grid.y = mat * (M/MBLK) + half. 256 threads; TXN=MBLK/CT; TYN=256/TXN; RT=RB/TYN.
// A smem: pitch 33 float4; strided row assignment. W smem: chunk-swizzled.
template <int M, int MBLK, int CT, int RB>
__global__ __launch_bounds__(256) void gemm_kernel(
    const float* __restrict__ A, int n,
    const float* __restrict__ W1, const float* __restrict__ b1, float* __restrict__ C1,
    const float* __restrict__ W2, const float* __restrict__ b2, float* __restrict__ C2)
{
    constexpr int K    = 128;
    constexpr int TXN  = MBLK / CT;     // 8
    constexpr int TYN  = 256 / TXN;     // 32
    constexpr int RT   = RB / TYN;      // 4
    constexpr int CP   = CT / 2;        // u64 accs per row: 4 or 2
    constexpr int NCH  = CT / 4;        // 16B chunks per thread: 2 or 1
    constexpr int NH   = M / MBLK;      // column-blocks per matrix
    constexpr int AP   = 33;            // A pitch in float4

    extern __shared__ float sm[];
    float4* As4 = reinterpret_cast<float4*>(sm);            // RB * AP float4
    float4* Ws4 = reinterpret_cast<float4*>(sm) + RB * AP;  // K * MBLK/4 swizzled

    const int mat  = blockIdx.y / NH;
    const int col0 = (blockIdx.y % NH) * MBLK;
    const float* __restrict__ W = mat ? W2 : W1;
    const float* __restrict__ b = mat ? b2 : b1;
    float* __restrict__       C = mat ? C2 : C1;

    const int tid  = threadIdx.x;
    const int row0 = blockIdx.x * RB;

    for (int i = tid; i < RB * 32; i += 256) {
        int r  = i >> 5;
        int c4 = i & 31;
        int gr_ = row0 + r;
        float4 v = make_float4(0.f, 0.f, 0.f, 0.f);
        if (gr_ < n) v = reinterpret_cast<const float4*>(A)[gr_ * 32 + c4];
        As4[r * AP + c4] = v;
    }
    for (int i = tid; i < K * (MBLK / 4); i += 256) {
        int k  = i / (MBLK / 4);
        int c4 = i % (MBLK / 4);
        int c  = c4 * 4;
        int txg   = c / CT;
        int chunk = (c % CT) >> 2;
        float4 v = reinterpret_cast<const float4*>(W + k * M + col0)[c4];
        Ws4[(k * NCH + chunk) * TXN + txg] = v;
    }
    __syncthreads();

    const int tx = tid % TXN;
    const int ty = tid / TXN;

    u64 acc[RT][CP];
    const u64 zz = pack2(0.f, 0.f);
#pragma unroll
    for (int i = 0; i < RT; i++)
#pragma unroll
        for (int j = 0; j < CP; j++) acc[i][j] = zz;

#pragma unroll 4
    for (int k4 = 0; k4 < K / 4; ++k4) {
        float4 av[RT];
#pragma unroll
        for (int i = 0; i < RT; i++)
            av[i] = As4[(ty + i * TYN) * AP + k4];   // strided rows: 1 wavefront

#pragma unroll
        for (int kk = 0; kk < 4; ++kk) {
            u64 wv[CP];
            const ulonglong2* wp = reinterpret_cast<const ulonglong2*>(
                Ws4 + (k4 * 4 + kk) * NCH * TXN);
#pragma unroll
            for (int jc = 0; jc < NCH; ++jc) {
                ulonglong2 u = wp[jc * TXN + tx];    // 128B contiguous per warp
                wv[jc * 2] = u.x;
                if constexpr (CP > 1) wv[jc * 2 + 1] = u.y;
            }
#pragma unroll
            for (int i = 0; i < RT; i++) {
                float a = (kk == 0) ? av[i].x : (kk == 1) ? av[i].y
                        : (kk == 2) ? av[i].z : av[i].w;
                u64 ap = pack2(a, a);
#pragma unroll
                for (int j = 0; j < CP; j++) ffma2(acc[i][j], ap, wv[j]);
            }
        }
    }

#pragma unroll
    for (int i = 0; i < RT; i++) {
        int r = row0 + ty + i * TYN;
        if (r < n) {
#pragma unroll
            for (int j = 0; j < CP; j++) {
                int c = col0 + tx * CT + j * 2;
                float2 v = unpack2(acc[i][j]);
                C[r * M + c]     = v.x + b[c];
                C[r * M + c + 1] = v.y + b[c + 1];
            }
        }
    }
}

// ---------------- layer 1: fused attention aggregation (warp per dst) ----------------
// Depth-3 software pipeline on the 512B gathers.
__global__ __launch_bounds__(256) void agg1_kernel(const float* __restrict__ att,
                                                   const float* __restrict__ bias) {
    const int lane = threadIdx.x & 31;
    const int d = blockIdx.x * (blockDim.x >> 5) + (threadIdx.x >> 5);
    if (d >= NN) return;

    const float4* __restrict__ gl4 = reinterpret_cast<const float4*>(g_gl1);
    const float4  grd = reinterpret_cast<const float4*>(g_gr1)[d * 32 + lane];
    const float4  at  = reinterpret_cast<const float4*>(att)[lane];

    float4 acc = make_float4(0.f, 0.f, 0.f, 0.f);
    float  den = 0.f;

    const unsigned start = g_rowstart[d];
    const unsigned deg   = g_rowstart[d + 1] - start;

    // items: 0 = self loop (src=d), 1..deg = CSR edges (src = csrc[start+i-1])
    int i1 = (deg > 0) ? g_csrc[start]     : d;
    int i2 = (deg > 1) ? g_csrc[start + 1] : d;
    float4 q0 = gl4[d  * 32 + lane];
    float4 q1 = gl4[i1 * 32 + lane];
    float4 q2 = gl4[i2 * 32 + lane];
    int s3 = (deg > 2) ? g_csrc[start + 2] : d;   // index of item 3

    for (unsigned j = 0; j <= deg; ++j) {
        float4 gc = q0;
        q0 = q1;
        q1 = q2;
        q2 = gl4[s3 * 32 + lane];                 // load item j+3 (clamped safe)
        s3 = (j + 4 <= deg) ? g_csrc[start + j + 3] : d;

        float m0 = gc.x + grd.x; m0 = (m0 > 0.f) ? m0 : NEG * m0;
        float m1 = gc.y + grd.y; m1 = (m1 > 0.f) ? m1 : NEG * m1;
        float m2 = gc.z + grd.z; m2 = (m2 > 0.f) ? m2 : NEG * m2;
        float m3 = gc.w + grd.w; m3 = (m3 > 0.f) ? m3 : NEG * m3;
        float p = at.x * m0 + at.y * m1 + at.z * m2 + at.w * m3;
        p += __shfl_xor_sync(0xffffffffu, p, 1);
        p += __shfl_xor_sync(0xffffffffu, p, 2);
        p += __shfl_xor_sync(0xffffffffu, p, 4);
        float w = __expf(p);
        acc.x += w * gc.x;
        acc.y += w * gc.y;
        acc.z += w * gc.z;
        acc.w += w * gc.w;
        den += w;
    }

    const float inv = 1.f / den;
    const float4 b = reinterpret_cast<const float4*>(bias)[lane];
    float v0 = acc.x * inv + b.x; v0 = (v0 > 0.f) ? v0 : expm1f(v0);
    float v1 = acc.y * inv + b.y; v1 = (v1 > 0.f) ? v1 : expm1f(v1);
    float v2 = acc.z * inv + b.z; v2 = (v2 > 0.f) ? v2 : expm1f(v2);
    float v3 = acc.w * inv + b.w; v3 = (v3 > 0.f) ? v3 : expm1f(v3);
    reinterpret_cast<float4*>(g_h1)[d * 32 + lane] = make_float4(v0, v1, v2, v3);
}

// ---------------- layer 2: aggregation, 4 dsts per warp (8 lanes / dst) -------------
__global__ __launch_bounds__(256) void agg2_kernel(const float* __restrict__ att,
                                                   const float* __restrict__ bias,
                                                   float* __restrict__ out) {
    const int lane = threadIdx.x & 31;
    const int grp  = lane >> 3;
    const int lg   = lane & 7;
    const int wid  = blockIdx.x * (blockDim.x >> 5) + (threadIdx.x >> 5);
    int d = wid * 4 + grp;
    const bool dvalid = (d < NN);
    if (d >= NN) d = NN - 1;

    const float4* __restrict__ gl4 = reinterpret_cast<const float4*>(g_gl2);
    const float4 grd  = reinterpret_cast<const float4*>(g_gr2)[d * 8 + lg];
    const float4 at   = reinterpret_cast<const float4*>(att)[lg];

    const unsigned start = g_rowstart[d];
    const unsigned deg   = dvalid ? (g_rowstart[d + 1] - start) : 0u;

    unsigned mdeg = deg;
#pragma unroll
    for (int off = 8; off < 32; off <<= 1) {
        unsigned o = __shfl_xor_sync(0xffffffffu, mdeg, off);
        mdeg = (o > mdeg) ? o : mdeg;
    }

    float4 acc = make_float4(0.f, 0.f, 0.f, 0.f);
    float  den = 0.f;

    int snext = (deg > 0) ? g_csrc[start] : d;
    float4 g = gl4[d * 8 + lg];

    for (unsigned j = 0; j <= mdeg; ++j) {
        float4 gc = g;
        int snn = (j + 2 <= deg) ? g_csrc[start + j + 1] : d;
        g = gl4[snext * 8 + lg];
        snext = snn;

        float m0 = gc.x + grd.x; m0 = (m0 > 0.f) ? m0 : NEG * m0;
        float m1 = gc.y + grd.y; m1 = (m1 > 0.f) ? m1 : NEG * m1;
        float m2 = gc.z + grd.z; m2 = (m2 > 0.f) ? m2 : NEG * m2;
        float m3 = gc.w + grd.w; m3 = (m3 > 0.f) ? m3 : NEG * m3;
        float p = at.x * m0 + at.y * m1 + at.z * m2 + at.w * m3;
        p += __shfl_xor_sync(0xffffffffu, p, 1);
        p += __shfl_xor_sync(0xffffffffu, p, 2);
        p += __shfl_xor_sync(0xffffffffu, p, 4);
        float w = (j <= deg) ? __expf(p) : 0.f;
        acc.x += w * gc.x;
        acc.y += w * gc.y;
        acc.z += w * gc.z;
        acc.w += w * gc.w;
        den += w;
    }

    if (dvalid) {
        const float inv = 1.f / den;
        const float4 b = reinterpret_cast<const float4*>(bias)[lg];
        reinterpret_cast<float4*>(out)[d * 8 + lg] =
            make_float4(acc.x * inv + b.x, acc.y * inv + b.y,
                        acc.z * inv + b.z, acc.w * inv + b.w);
    }
}

// ---------------- launch ----------------
extern "C" void kernel_launch(void* const* d_in, const int* in_sizes, int n_in,
                              void* d_out, int out_size) {
    const float* x    = (const float*)d_in[0];
    const int*   ei   = (const int*)d_in[1];
    const float* Wl1  = (const float*)d_in[2];
    const float* bl1  = (const float*)d_in[3];
    const float* Wr1  = (const float*)d_in[4];
    const float* br1  = (const float*)d_in[5];
    const float* att1 = (const float*)d_in[6];
    const float* bias1= (const float*)d_in[7];
    const float* Wl2  = (const float*)d_in[8];
    const float* bl2  = (const float*)d_in[9];
    const float* Wr2  = (const float*)d_in[10];
    const float* br2  = (const float*)d_in[11];
    const float* att2 = (const float*)d_in[12];
    const float* bias2= (const float*)d_in[13];
    float* out = (float*)d_out;

    // gemm1: M=128, MBLK=64, CT=8, RB=128 -> smem 128*33*16 + 128*64*4 = 100352
    // gemm2: M=32,  MBLK=32, CT=4, RB=128 -> smem 128*33*16 + 128*32*4 = 83968
    const int smem1 = 128 * 33 * 16 + 128 * 64 * 4;
    const int smem2 = 128 * 33 * 16 + 128 * 32 * 4;
    cudaFuncSetAttribute((gemm_kernel<128, 64, 8, 128>),
                         cudaFuncAttributeMaxDynamicSharedMemorySize, smem1);
    cudaFuncSetAttribute((gemm_kernel<32, 32, 4, 128>),
                         cudaFuncAttributeMaxDynamicSharedMemorySize, smem2);

    float *gl1p, *gr1p, *h1p, *gl2p, *gr2p;
    cudaGetSymbolAddress((void**)&gl1p, g_gl1);
    cudaGetSymbolAddress((void**)&gr1p, g_gr1);
    cudaGetSymbolAddress((void**)&h1p,  g_h1);
    cudaGetSymbolAddress((void**)&gl2p, g_gl2);
    cudaGetSymbolAddress((void**)&gr2p, g_gr2);

    // slots 1-3: CSR; slot 4: gemm1 (profiled by ncu)
    csr_hist_kernel<<<(EE + 255) / 256, 256>>>(ei);
    csr_scan_kernel<<<1, 1024>>>();
    csr_fill_kernel<<<(EE + 255) / 256, 256>>>(ei);
    gemm_kernel<128, 64, 8, 128><<<dim3((NN + 127) / 128, 4), 256, smem1>>>(
        x, NN, Wl1, bl1, gl1p, Wr1, br1, gr1p);

    agg1_kernel<<<(NN + 7) / 8, 256>>>(att1, bias1);

    gemm_kernel<32, 32, 4, 128><<<dim3((NN + 127) / 128, 2), 256, smem2>>>(
        h1p, NN, Wl2, bl2, gl2p, Wr2, br2, gr2p);
    agg2_kernel<<<(NN + 31) / 32, 256>>>(att2, bias2, out);
}

// round 10
// speedup vs baseline: 1.1674x; 1.0535x over previous
#include <cuda_runtime.h>

#define NN 50000
#define EE 800000
#define NEG 0.2f

typedef unsigned long long u64;

// ---------------- scratch (static device globals; no allocation) ----------------
__device__ __align__(16) float    g_gl1[NN * 128];
__device__ __align__(16) float    g_gr1[NN * 128];
__device__ __align__(16) float    g_h1 [NN * 128];
__device__ __align__(16) float    g_gl2[NN * 32];
__device__ __align__(16) float    g_gr2[NN * 32];
// CSR by dst
__device__ unsigned g_cnt[NN];          // statically zero; scan re-zeroes each call
__device__ unsigned g_rowstart[NN + 1];
__device__ unsigned g_cursor[NN];
__device__ int      g_csrc[EE];

// ---------------- f32x2 helpers ----------------
__device__ __forceinline__ u64 pack2(float lo, float hi) {
    u64 r;
    asm("mov.b64 %0, {%1, %2};" : "=l"(r) : "f"(lo), "f"(hi));
    return r;
}
__device__ __forceinline__ float2 unpack2(u64 v) {
    float2 r;
    asm("mov.b64 {%0, %1}, %2;" : "=f"(r.x), "=f"(r.y) : "l"(v));
    return r;
}
__device__ __forceinline__ void ffma2(u64& d, u64 a, u64 b) {
    asm("fma.rn.f32x2 %0, %1, %2, %0;" : "+l"(d) : "l"(a), "l"(b));
}

// ---------------- CSR build ----------------
__global__ void csr_hist_kernel(const int* __restrict__ ei) {
    int i = blockIdx.x * blockDim.x + threadIdx.x;
    if (i < EE) atomicAdd(&g_cnt[ei[EE + i]], 1u);
}
// single-block exclusive scan; consumes AND re-zeroes g_cnt (ready for next call)
__global__ __launch_bounds__(1024) void csr_scan_kernel() {
    __shared__ unsigned s[1024];
    const int T = 1024;
    const int CH = (NN + T - 1) / T;
    int t = threadIdx.x;
    int base = t * CH;
    unsigned sum = 0;
    for (int i = 0; i < CH; i++) {
        int j = base + i;
        if (j < NN) sum += g_cnt[j];
    }
    s[t] = sum;
    __syncthreads();
    for (int off = 1; off < T; off <<= 1) {
        unsigned u = (t >= off) ? s[t - off] : 0u;
        __syncthreads();
        s[t] += u;
        __syncthreads();
    }
    unsigned run = s[t] - sum;
    for (int i = 0; i < CH; i++) {
        int j = base + i;
        if (j < NN) {
            unsigned c = g_cnt[j];
            g_cnt[j] = 0u;            // self-reset for the next graph replay
            g_rowstart[j] = run;
            g_cursor[j]   = run;
            run += c;
        }
    }
    if (t == T - 1) g_rowstart[NN] = run;   // == EE
}
__global__ void csr_fill_kernel(const int* __restrict__ ei) {
    int i = blockIdx.x * blockDim.x + threadIdx.x;
    if (i < EE) {
        int d = ei[EE + i];
        unsigned pos = atomicAdd(&g_cursor[d], 1u);
        g_csrc[pos] = ei[i];
    }
}

// ---------------- layer-1 GEMM: 8x8 thread tile, K-split A staging -----------------
// A:[n,128], W:[128,128]. Block: 128 rows x full 128 cols of ONE matrix (blockIdx.y).
// 256 threads: tx = tid%16 (8 cols each), ty = tid/16 (8 rows strided by 16).
// A staged in two K-halves of 64 (pitch 17 float4); W resident all K (swizzled).
__global__ __launch_bounds__(256, 2) void gemm1_kernel(
    const float* __restrict__ A, int n,
    const float* __restrict__ W1, const float* __restrict__ b1, float* __restrict__ C1,
    const float* __restrict__ W2, const float* __restrict__ b2, float* __restrict__ C2)
{
    constexpr int M   = 128;
    constexpr int RB  = 128;
    constexpr int AP  = 17;          // A pitch in float4 (16 data + 1 pad)

    extern __shared__ float sm[];
    float4* As4 = reinterpret_cast<float4*>(sm);            // RB * AP
    float4* Ws4 = reinterpret_cast<float4*>(sm) + RB * AP;  // 128 * 32 swizzled

    const float* __restrict__ W = blockIdx.y ? W2 : W1;
    const float* __restrict__ b = blockIdx.y ? b2 : b1;
    float* __restrict__       C = blockIdx.y ? C2 : C1;

    const int tid  = threadIdx.x;
    const int row0 = blockIdx.x * RB;
    const int tx   = tid & 15;
    const int ty   = tid >> 4;

    // load W swizzled: src (k, c) -> dst float4 slot (k*2 + chunk)*16 + txg
    for (int i = tid; i < 128 * 32; i += 256) {
        int k  = i >> 5;
        int c4 = i & 31;
        int c  = c4 * 4;
        int txg   = c >> 3;          // c / 8
        int chunk = (c & 7) >> 2;    // 0 or 1
        float4 v = reinterpret_cast<const float4*>(W + k * M)[c4];
        Ws4[(k * 2 + chunk) * 16 + txg] = v;
    }

    const float4* __restrict__ A4 = reinterpret_cast<const float4*>(A);

    u64 acc[8][4];
    const u64 zz = pack2(0.f, 0.f);
#pragma unroll
    for (int i = 0; i < 8; i++)
#pragma unroll
        for (int j = 0; j < 4; j++) acc[i][j] = zz;

    for (int kh = 0; kh < 2; ++kh) {
        __syncthreads();
        // stage A K-half: 128 rows x 16 float4, coalesced
        for (int i = tid; i < RB * 16; i += 256) {
            int r  = i >> 4;
            int c4 = i & 15;
            int gr_ = row0 + r;
            float4 v = make_float4(0.f, 0.f, 0.f, 0.f);
            if (gr_ < n) v = A4[gr_ * 32 + kh * 16 + c4];
            As4[r * AP + c4] = v;
        }
        __syncthreads();

#pragma unroll 4
        for (int k4 = 0; k4 < 16; ++k4) {
            const int kg = kh * 16 + k4;    // global k4
            float4 av[8];
#pragma unroll
            for (int i = 0; i < 8; i++)
                av[i] = As4[(ty + i * 16) * AP + k4];   // 2 addrs/warp: broadcast

#pragma unroll
            for (int kk = 0; kk < 4; ++kk) {
                const int k = kg * 4 + kk;
                u64 wv[4];
#pragma unroll
                for (int jc = 0; jc < 2; ++jc) {
                    ulonglong2 u = reinterpret_cast<const ulonglong2*>(Ws4)
                        [(k * 2 + jc) * 16 + tx];       // 256B/warp contiguous
                    wv[jc * 2]     = u.x;
                    wv[jc * 2 + 1] = u.y;
                }
#pragma unroll
                for (int i = 0; i < 8; i++) {
                    float a = (kk == 0) ? av[i].x : (kk == 1) ? av[i].y
                            : (kk == 2) ? av[i].z : av[i].w;
                    u64 ap = pack2(a, a);
#pragma unroll
                    for (int j = 0; j < 4; j++) ffma2(acc[i][j], ap, wv[j]);
                }
            }
        }
    }

#pragma unroll
    for (int i = 0; i < 8; i++) {
        int r = row0 + ty + i * 16;
        if (r < n) {
#pragma unroll
            for (int j = 0; j < 4; j++) {
                int c = tx * 8 + j * 2;
                float2 v = unpack2(acc[i][j]);
                C[r * M + c]     = v.x + b[c];
                C[r * M + c + 1] = v.y + b[c + 1];
            }
        }
    }
}

// ---------------- layer-2 GEMM (small M): round-7 template instance ----------------
template <int M, int MBLK, int CT, int RB>
__global__ __launch_bounds__(256) void gemm_kernel(
    const float* __restrict__ A, int n,
    const float* __restrict__ W1, const float* __restrict__ b1, float* __restrict__ C1,
    const float* __restrict__ W2, const float* __restrict__ b2, float* __restrict__ C2)
{
    constexpr int K    = 128;
    constexpr int TXN  = MBLK / CT;
    constexpr int TYN  = 256 / TXN;
    constexpr int RT   = RB / TYN;
    constexpr int CP   = CT / 2;
    constexpr int NCH  = CT / 4;
    constexpr int NH   = M / MBLK;
    constexpr int AP   = 33;

    extern __shared__ float sm[];
    float4* As4 = reinterpret_cast<float4*>(sm);
    float4* Ws4 = reinterpret_cast<float4*>(sm) + RB * AP;

    const int mat  = blockIdx.y / NH;
    const int col0 = (blockIdx.y % NH) * MBLK;
    const float* __restrict__ W = mat ? W2 : W1;
    const float* __restrict__ b = mat ? b2 : b1;
    float* __restrict__       C = mat ? C2 : C1;

    const int tid  = threadIdx.x;
    const int row0 = blockIdx.x * RB;

    for (int i = tid; i < RB * 32; i += 256) {
        int r  = i >> 5;
        int c4 = i & 31;
        int gr_ = row0 + r;
        float4 v = make_float4(0.f, 0.f, 0.f, 0.f);
        if (gr_ < n) v = reinterpret_cast<const float4*>(A)[gr_ * 32 + c4];
        As4[r * AP + c4] = v;
    }
    for (int i = tid; i < K * (MBLK / 4); i += 256) {
        int k  = i / (MBLK / 4);
        int c4 = i % (MBLK / 4);
        int c  = c4 * 4;
        int txg   = c / CT;
        int chunk = (c % CT) >> 2;
        float4 v = reinterpret_cast<const float4*>(W + k * M + col0)[c4];
        Ws4[(k * NCH + chunk) * TXN + txg] = v;
    }
    __syncthreads();

    const int tx = tid % TXN;
    const int ty = tid / TXN;

    u64 acc[RT][CP];
    const u64 zz = pack2(0.f, 0.f);
#pragma unroll
    for (int i = 0; i < RT; i++)
#pragma unroll
        for (int j = 0; j < CP; j++) acc[i][j] = zz;

#pragma unroll 4
    for (int k4 = 0; k4 < K / 4; ++k4) {
        float4 av[RT];
#pragma unroll
        for (int i = 0; i < RT; i++)
            av[i] = As4[(ty + i * TYN) * AP + k4];

#pragma unroll
        for (int kk = 0; kk < 4; ++kk) {
            u64 wv[CP];
            const ulonglong2* wp = reinterpret_cast<const ulonglong2*>(
                Ws4 + (k4 * 4 + kk) * NCH * TXN);
#pragma unroll
            for (int jc = 0; jc < NCH; ++jc) {
                ulonglong2 u = wp[jc * TXN + tx];
                wv[jc * 2] = u.x;
                if constexpr (CP > 1) wv[jc * 2 + 1] = u.y;
            }
#pragma unroll
            for (int i = 0; i < RT; i++) {
                float a = (kk == 0) ? av[i].x : (kk == 1) ? av[i].y
                        : (kk == 2) ? av[i].z : av[i].w;
                u64 ap = pack2(a, a);
#pragma unroll
                for (int j = 0; j < CP; j++) ffma2(acc[i][j], ap, wv[j]);
            }
        }
    }

#pragma unroll
    for (int i = 0; i < RT; i++) {
        int r = row0 + ty + i * TYN;
        if (r < n) {
#pragma unroll
            for (int j = 0; j < CP; j++) {
                int c = col0 + tx * CT + j * 2;
                float2 v = unpack2(acc[i][j]);
                C[r * M + c]     = v.x + b[c];
                C[r * M + c + 1] = v.y + b[c + 1];
            }
        }
    }
}

// ---------------- layer 1: fused attention aggregation (warp per dst, depth-2) -------
__global__ __launch_bounds__(256) void agg1_kernel(const float* __restrict__ att,
                                                   const float* __restrict__ bias) {
    const int lane = threadIdx.x & 31;
    const int d = blockIdx.x * (blockDim.x >> 5) + (threadIdx.x >> 5);
    if (d >= NN) return;

    const float4* __restrict__ gl4 = reinterpret_cast<const float4*>(g_gl1);
    const float4  grd = reinterpret_cast<const float4*>(g_gr1)[d * 32 + lane];
    const float4  at  = reinterpret_cast<const float4*>(att)[lane];

    float4 acc = make_float4(0.f, 0.f, 0.f, 0.f);
    float  den = 0.f;

    const unsigned start = g_rowstart[d];
    const unsigned deg   = g_rowstart[d + 1] - start;

    int s1 = (deg > 0) ? g_csrc[start]     : d;
    int s2 = (deg > 1) ? g_csrc[start + 1] : d;
    float4 gcur  = gl4[d  * 32 + lane];
    float4 gnext = gl4[s1 * 32 + lane];

    for (unsigned j = 0; j <= deg; ++j) {
        float4 gnn = gl4[s2 * 32 + lane];
        s2 = (j + 3 <= deg) ? g_csrc[start + j + 2] : d;

        float m0 = gcur.x + grd.x; m0 = (m0 > 0.f) ? m0 : NEG * m0;
        float m1 = gcur.y + grd.y; m1 = (m1 > 0.f) ? m1 : NEG * m1;
        float m2 = gcur.z + grd.z; m2 = (m2 > 0.f) ? m2 : NEG * m2;
        float m3 = gcur.w + grd.w; m3 = (m3 > 0.f) ? m3 : NEG * m3;
        float p = at.x * m0 + at.y * m1 + at.z * m2 + at.w * m3;
        p += __shfl_xor_sync(0xffffffffu, p, 1);
        p += __shfl_xor_sync(0xffffffffu, p, 2);
        p += __shfl_xor_sync(0xffffffffu, p, 4);
        float w = __expf(p);
        acc.x += w * gcur.x;
        acc.y += w * gcur.y;
        acc.z += w * gcur.z;
        acc.w += w * gcur.w;
        den += w;

        gcur = gnext;
        gnext = gnn;
    }

    const float inv = 1.f / den;
    const float4 b = reinterpret_cast<const float4*>(bias)[lane];
    float v0 = acc.x * inv + b.x; v0 = (v0 > 0.f) ? v0 : expm1f(v0);
    float v1 = acc.y * inv + b.y; v1 = (v1 > 0.f) ? v1 : expm1f(v1);
    float v2 = acc.z * inv + b.z; v2 = (v2 > 0.f) ? v2 : expm1f(v2);
    float v3 = acc.w * inv + b.w; v3 = (v3 > 0.f) ? v3 : expm1f(v3);
    reinterpret_cast<float4*>(g_h1)[d * 32 + lane] = make_float4(v0, v1, v2, v3);
}

// ---------------- layer 2: aggregation, 4 dsts per warp (8 lanes / dst) -------------
__global__ __launch_bounds__(256) void agg2_kernel(const float* __restrict__ att,
                                                   const float* __restrict__ bias,
                                                   float* __restrict__ out) {
    const int lane = threadIdx.x & 31;
    const int grp  = lane >> 3;
    const int lg   = lane & 7;
    const int wid  = blockIdx.x * (blockDim.x >> 5) + (threadIdx.x >> 5);
    int d = wid * 4 + grp;
    const bool dvalid = (d < NN);
    if (d >= NN) d = NN - 1;

    const float4* __restrict__ gl4 = reinterpret_cast<const float4*>(g_gl2);
    const float4 grd  = reinterpret_cast<const float4*>(g_gr2)[d * 8 + lg];
    const float4 at   = reinterpret_cast<const float4*>(att)[lg];

    const unsigned start = g_rowstart[d];
    const unsigned deg   = dvalid ? (g_rowstart[d + 1] - start) : 0u;

    unsigned mdeg = deg;
#pragma unroll
    for (int off = 8; off < 32; off <<= 1) {
        unsigned o = __shfl_xor_sync(0xffffffffu, mdeg, off);
        mdeg = (o > mdeg) ? o : mdeg;
    }

    float4 acc = make_float4(0.f, 0.f, 0.f, 0.f);
    float  den = 0.f;

    int snext = (deg > 0) ? g_csrc[start] : d;
    float4 g = gl4[d * 8 + lg];

    for (unsigned j = 0; j <= mdeg; ++j) {
        float4 gc = g;
        int snn = (j + 2 <= deg) ? g_csrc[start + j + 1] : d;
        g = gl4[snext * 8 + lg];
        snext = snn;

        float m0 = gc.x + grd.x; m0 = (m0 > 0.f) ? m0 : NEG * m0;
        float m1 = gc.y + grd.y; m1 = (m1 > 0.f) ? m1 : NEG * m1;
        float m2 = gc.z + grd.z; m2 = (m2 > 0.f) ? m2 : NEG * m2;
        float m3 = gc.w + grd.w; m3 = (m3 > 0.f) ? m3 : NEG * m3;
        float p = at.x * m0 + at.y * m1 + at.z * m2 + at.w * m3;
        p += __shfl_xor_sync(0xffffffffu, p, 1);
        p += __shfl_xor_sync(0xffffffffu, p, 2);
        p += __shfl_xor_sync(0xffffffffu, p, 4);
        float w = (j <= deg) ? __expf(p) : 0.f;
        acc.x += w * gc.x;
        acc.y += w * gc.y;
        acc.z += w * gc.z;
        acc.w += w * gc.w;
        den += w;
    }

    if (dvalid) {
        const float inv = 1.f / den;
        const float4 b = reinterpret_cast<const float4*>(bias)[lg];
        reinterpret_cast<float4*>(out)[d * 8 + lg] =
            make_float4(acc.x * inv + b.x, acc.y * inv + b.y,
                        acc.z * inv + b.z, acc.w * inv + b.w);
    }
}

// ---------------- launch ----------------
extern "C" void kernel_launch(void* const* d_in, const int* in_sizes, int n_in,
                              void* d_out, int out_size) {
    const float* x    = (const float*)d_in[0];
    const int*   ei   = (const int*)d_in[1];
    const float* Wl1  = (const float*)d_in[2];
    const float* bl1  = (const float*)d_in[3];
    const float* Wr1  = (const float*)d_in[4];
    const float* br1  = (const float*)d_in[5];
    const float* att1 = (const float*)d_in[6];
    const float* bias1= (const float*)d_in[7];
    const float* Wl2  = (const float*)d_in[8];
    const float* bl2  = (const float*)d_in[9];
    const float* Wr2  = (const float*)d_in[10];
    const float* br2  = (const float*)d_in[11];
    const float* att2 = (const float*)d_in[12];
    const float* bias2= (const float*)d_in[13];
    float* out = (float*)d_out;

    // gemm1: A 128*17*16 = 34816 + W 128*128*4 = 65536 -> 100352 (2 blocks/SM)
    // gemm2: M=32, MBLK=32, CT=4, RB=128 -> 128*33*16 + 128*32*4 = 83968
    const int smem1 = 128 * 17 * 16 + 128 * 128 * 4;
    const int smem2 = 128 * 33 * 16 + 128 * 32 * 4;
    cudaFuncSetAttribute(gemm1_kernel,
                         cudaFuncAttributeMaxDynamicSharedMemorySize, smem1);
    cudaFuncSetAttribute((gemm_kernel<32, 32, 4, 128>),
                         cudaFuncAttributeMaxDynamicSharedMemorySize, smem2);

    float *gl1p, *gr1p, *h1p, *gl2p, *gr2p;
    cudaGetSymbolAddress((void**)&gl1p, g_gl1);
    cudaGetSymbolAddress((void**)&gr1p, g_gr1);
    cudaGetSymbolAddress((void**)&h1p,  g_h1);
    cudaGetSymbolAddress((void**)&gl2p, g_gl2);
    cudaGetSymbolAddress((void**)&gr2p, g_gr2);

    // slots 1-3: CSR; slot 4: gemm1 (profiled by ncu)
    csr_hist_kernel<<<(EE + 255) / 256, 256>>>(ei);
    csr_scan_kernel<<<1, 1024>>>();
    csr_fill_kernel<<<(EE + 255) / 256, 256>>>(ei);
    gemm1_kernel<<<dim3((NN + 127) / 128, 2), 256, smem1>>>(
        x, NN, Wl1, bl1, gl1p, Wr1, br1, gr1p);

    agg1_kernel<<<(NN + 7) / 8, 256>>>(att1, bias1);

    gemm_kernel<32, 32, 4, 128><<<dim3((NN + 127) / 128, 2), 256, smem2>>>(
        h1p, NN, Wl2, bl2, gl2p, Wr2, br2, gr2p);
    agg2_kernel<<<(NN + 31) / 32, 256>>>(att2, bias2, out);
}

// round 11
// speedup vs baseline: 1.2013x; 1.0290x over previous
#include <cuda_runtime.h>

#define NN 50000
#define EE 800000
#define NEG 0.2f

typedef unsigned long long u64;

// ---------------- scratch (static device globals; no allocation) ----------------
__device__ __align__(16) float    g_gl1[NN * 128];
__device__ __align__(16) float    g_gr1[NN * 128];
__device__ __align__(16) float    g_h1 [NN * 128];
__device__ __align__(16) float    g_gl2[NN * 32];
__device__ __align__(16) float    g_gr2[NN * 32];
// CSR by dst
__device__ unsigned g_cnt[NN];          // statically zero; scan re-zeroes each call
__device__ unsigned g_rowstart[NN + 1];
__device__ unsigned g_cursor[NN];
__device__ int      g_csrc[EE];

// ---------------- f32x2 helpers ----------------
__device__ __forceinline__ u64 pack2(float lo, float hi) {
    u64 r;
    asm("mov.b64 %0, {%1, %2};" : "=l"(r) : "f"(lo), "f"(hi));
    return r;
}
__device__ __forceinline__ float2 unpack2(u64 v) {
    float2 r;
    asm("mov.b64 {%0, %1}, %2;" : "=f"(r.x), "=f"(r.y) : "l"(v));
    return r;
}
__device__ __forceinline__ void ffma2(u64& d, u64 a, u64 b) {
    asm("fma.rn.f32x2 %0, %1, %2, %0;" : "+l"(d) : "l"(a), "l"(b));
}

// ---------------- CSR scan / fill ----------------
// single-block exclusive scan; consumes AND re-zeroes g_cnt (ready for next call)
__global__ __launch_bounds__(1024) void csr_scan_kernel() {
    __shared__ unsigned s[1024];
    const int T = 1024;
    const int CH = (NN + T - 1) / T;
    int t = threadIdx.x;
    int base = t * CH;
    unsigned sum = 0;
    for (int i = 0; i < CH; i++) {
        int j = base + i;
        if (j < NN) sum += g_cnt[j];
    }
    s[t] = sum;
    __syncthreads();
    for (int off = 1; off < T; off <<= 1) {
        unsigned u = (t >= off) ? s[t - off] : 0u;
        __syncthreads();
        s[t] += u;
        __syncthreads();
    }
    unsigned run = s[t] - sum;
    for (int i = 0; i < CH; i++) {
        int j = base + i;
        if (j < NN) {
            unsigned c = g_cnt[j];
            g_cnt[j] = 0u;            // self-reset for the next graph replay
            g_rowstart[j] = run;
            g_cursor[j]   = run;
            run += c;
        }
    }
    if (t == T - 1) g_rowstart[NN] = run;   // == EE
}
__global__ void csr_fill_kernel(const int* __restrict__ ei) {
    int i = blockIdx.x * blockDim.x + threadIdx.x;
    if (i < EE) {
        int d = ei[EE + i];
        unsigned pos = atomicAdd(&g_cursor[d], 1u);
        g_csrc[pos] = ei[i];
    }
}

// ---------------- layer-1 GEMM + fused edge histogram -----------------------------
// grid = (391, 5). y in 0..3: GEMM block (mat = y>>1, col half = y&1), computes
// 128 rows x 64 cols. y == 4: edge histogram (independent; overlaps the GEMM).
// GEMM: 256 threads, tx=tid&7 (8 cols), ty=tid>>3 (4 rows strided 32).
// A staged in two K-halves (pitch 17 float4); W full-K for the 64-col half, swizzled.
__global__ __launch_bounds__(256, 3) void gemm1_hist_kernel(
    const float* __restrict__ A, int n,
    const float* __restrict__ W1, const float* __restrict__ b1, float* __restrict__ C1,
    const float* __restrict__ W2, const float* __restrict__ b2, float* __restrict__ C2,
    const int* __restrict__ ei)
{
    if (blockIdx.y == 4) {
        int stride = gridDim.x * blockDim.x;
        for (int i = blockIdx.x * blockDim.x + threadIdx.x; i < EE; i += stride)
            atomicAdd(&g_cnt[ei[EE + i]], 1u);
        return;
    }

    constexpr int M  = 128;
    constexpr int RB = 128;
    constexpr int AP = 17;           // A pitch in float4 (16 data + 1 pad)

    extern __shared__ float sm[];
    float4* As4 = reinterpret_cast<float4*>(sm);            // 128 * 17
    float4* Ws4 = reinterpret_cast<float4*>(sm) + RB * AP;  // 128 * 16 swizzled

    const int mat  = blockIdx.y >> 1;
    const int col0 = (blockIdx.y & 1) * 64;
    const float* __restrict__ W = mat ? W2 : W1;
    const float* __restrict__ b = mat ? b2 : b1;
    float* __restrict__       C = mat ? C2 : C1;

    const int tid  = threadIdx.x;
    const int row0 = blockIdx.x * RB;
    const int tx   = tid & 7;
    const int ty   = tid >> 3;

    // load W column-half, full K, swizzled: (k, c4) -> (k*2 + (c4&1))*8 + (c4>>1)
    for (int i = tid; i < 128 * 16; i += 256) {
        int k  = i >> 4;
        int c4 = i & 15;
        float4 v = reinterpret_cast<const float4*>(W + k * M + col0)[c4];
        Ws4[(k * 2 + (c4 & 1)) * 8 + (c4 >> 1)] = v;
    }

    const float4* __restrict__ A4 = reinterpret_cast<const float4*>(A);

    u64 acc[4][4];
    const u64 zz = pack2(0.f, 0.f);
#pragma unroll
    for (int i = 0; i < 4; i++)
#pragma unroll
        for (int j = 0; j < 4; j++) acc[i][j] = zz;

    for (int kh = 0; kh < 2; ++kh) {
        __syncthreads();
        // stage A K-half: 128 rows x 16 float4, coalesced
        for (int i = tid; i < RB * 16; i += 256) {
            int r  = i >> 4;
            int c4 = i & 15;
            int gr_ = row0 + r;
            float4 v = make_float4(0.f, 0.f, 0.f, 0.f);
            if (gr_ < n) v = A4[gr_ * 32 + kh * 16 + c4];
            As4[r * AP + c4] = v;
        }
        __syncthreads();

#pragma unroll 2
        for (int k4 = 0; k4 < 16; ++k4) {
            float4 av[4];
#pragma unroll
            for (int i = 0; i < 4; i++)
                av[i] = As4[(ty + i * 32) * AP + k4];   // 4 addrs/warp: broadcast

#pragma unroll
            for (int kk = 0; kk < 4; ++kk) {
                const int k = (kh * 16 + k4) * 4 + kk;
                u64 wv[4];
                const ulonglong2* wp =
                    reinterpret_cast<const ulonglong2*>(Ws4 + k * 16);
#pragma unroll
                for (int jc = 0; jc < 2; ++jc) {
                    ulonglong2 u = wp[jc * 8 + tx];     // 128B/warp contiguous
                    wv[jc * 2]     = u.x;
                    wv[jc * 2 + 1] = u.y;
                }
#pragma unroll
                for (int i = 0; i < 4; i++) {
                    float a = (kk == 0) ? av[i].x : (kk == 1) ? av[i].y
                            : (kk == 2) ? av[i].z : av[i].w;
                    u64 ap = pack2(a, a);
#pragma unroll
                    for (int j = 0; j < 4; j++) ffma2(acc[i][j], ap, wv[j]);
                }
            }
        }
    }

#pragma unroll
    for (int i = 0; i < 4; i++) {
        int r = row0 + ty + i * 32;
        if (r < n) {
#pragma unroll
            for (int j = 0; j < 4; j++) {
                int c = col0 + tx * 8 + j * 2;
                float2 v = unpack2(acc[i][j]);
                C[r * M + c]     = v.x + b[c];
                C[r * M + c + 1] = v.y + b[c + 1];
            }
        }
    }
}

// ---------------- layer-2 GEMM (small M) -------------------------------------------
template <int M, int MBLK, int CT, int RB>
__global__ __launch_bounds__(256) void gemm_kernel(
    const float* __restrict__ A, int n,
    const float* __restrict__ W1, const float* __restrict__ b1, float* __restrict__ C1,
    const float* __restrict__ W2, const float* __restrict__ b2, float* __restrict__ C2)
{
    constexpr int K    = 128;
    constexpr int TXN  = MBLK / CT;
    constexpr int TYN  = 256 / TXN;
    constexpr int RT   = RB / TYN;
    constexpr int CP   = CT / 2;
    constexpr int NCH  = CT / 4;
    constexpr int NH   = M / MBLK;
    constexpr int AP   = 33;

    extern __shared__ float sm[];
    float4* As4 = reinterpret_cast<float4*>(sm);
    float4* Ws4 = reinterpret_cast<float4*>(sm) + RB * AP;

    const int mat  = blockIdx.y / NH;
    const int col0 = (blockIdx.y % NH) * MBLK;
    const float* __restrict__ W = mat ? W2 : W1;
    const float* __restrict__ b = mat ? b2 : b1;
    float* __restrict__       C = mat ? C2 : C1;

    const int tid  = threadIdx.x;
    const int row0 = blockIdx.x * RB;

    for (int i = tid; i < RB * 32; i += 256) {
        int r  = i >> 5;
        int c4 = i & 31;
        int gr_ = row0 + r;
        float4 v = make_float4(0.f, 0.f, 0.f, 0.f);
        if (gr_ < n) v = reinterpret_cast<const float4*>(A)[gr_ * 32 + c4];
        As4[r * AP + c4] = v;
    }
    for (int i = tid; i < K * (MBLK / 4); i += 256) {
        int k  = i / (MBLK / 4);
        int c4 = i % (MBLK / 4);
        int c  = c4 * 4;
        int txg   = c / CT;
        int chunk = (c % CT) >> 2;
        float4 v = reinterpret_cast<const float4*>(W + k * M + col0)[c4];
        Ws4[(k * NCH + chunk) * TXN + txg] = v;
    }
    __syncthreads();

    const int tx = tid % TXN;
    const int ty = tid / TXN;

    u64 acc[RT][CP];
    const u64 zz = pack2(0.f, 0.f);
#pragma unroll
    for (int i = 0; i < RT; i++)
#pragma unroll
        for (int j = 0; j < CP; j++) acc[i][j] = zz;

#pragma unroll 4
    for (int k4 = 0; k4 < K / 4; ++k4) {
        float4 av[RT];
#pragma unroll
        for (int i = 0; i < RT; i++)
            av[i] = As4[(ty + i * TYN) * AP + k4];

#pragma unroll
        for (int kk = 0; kk < 4; ++kk) {
            u64 wv[CP];
            const ulonglong2* wp = reinterpret_cast<const ulonglong2*>(
                Ws4 + (k4 * 4 + kk) * NCH * TXN);
#pragma unroll
            for (int jc = 0; jc < NCH; ++jc) {
                ulonglong2 u = wp[jc * TXN + tx];
                wv[jc * 2] = u.x;
                if constexpr (CP > 1) wv[jc * 2 + 1] = u.y;
            }
#pragma unroll
            for (int i = 0; i < RT; i++) {
                float a = (kk == 0) ? av[i].x : (kk == 1) ? av[i].y
                        : (kk == 2) ? av[i].z : av[i].w;
                u64 ap = pack2(a, a);
#pragma unroll
                for (int j = 0; j < CP; j++) ffma2(acc[i][j], ap, wv[j]);
            }
        }
    }

#pragma unroll
    for (int i = 0; i < RT; i++) {
        int r = row0 + ty + i * TYN;
        if (r < n) {
#pragma unroll
            for (int j = 0; j < CP; j++) {
                int c = col0 + tx * CT + j * 2;
                float2 v = unpack2(acc[i][j]);
                C[r * M + c]     = v.x + b[c];
                C[r * M + c + 1] = v.y + b[c + 1];
            }
        }
    }
}

// ---------------- layer 1: fused attention aggregation (warp per dst, depth-2) -------
__global__ __launch_bounds__(256) void agg1_kernel(const float* __restrict__ att,
                                                   const float* __restrict__ bias) {
    const int lane = threadIdx.x & 31;
    const int d = blockIdx.x * (blockDim.x >> 5) + (threadIdx.x >> 5);
    if (d >= NN) return;

    const float4* __restrict__ gl4 = reinterpret_cast<const float4*>(g_gl1);
    const float4  grd = reinterpret_cast<const float4*>(g_gr1)[d * 32 + lane];
    const float4  at  = reinterpret_cast<const float4*>(att)[lane];

    float4 acc = make_float4(0.f, 0.f, 0.f, 0.f);
    float  den = 0.f;

    const unsigned start = g_rowstart[d];
    const unsigned deg   = g_rowstart[d + 1] - start;

    int s1 = (deg > 0) ? g_csrc[start]     : d;
    int s2 = (deg > 1) ? g_csrc[start + 1] : d;
    float4 gcur  = gl4[d  * 32 + lane];
    float4 gnext = gl4[s1 * 32 + lane];

    for (unsigned j = 0; j <= deg; ++j) {
        float4 gnn = gl4[s2 * 32 + lane];
        s2 = (j + 3 <= deg) ? g_csrc[start + j + 2] : d;

        float m0 = gcur.x + grd.x; m0 = (m0 > 0.f) ? m0 : NEG * m0;
        float m1 = gcur.y + grd.y; m1 = (m1 > 0.f) ? m1 : NEG * m1;
        float m2 = gcur.z + grd.z; m2 = (m2 > 0.f) ? m2 : NEG * m2;
        float m3 = gcur.w + grd.w; m3 = (m3 > 0.f) ? m3 : NEG * m3;
        float p = at.x * m0 + at.y * m1 + at.z * m2 + at.w * m3;
        p += __shfl_xor_sync(0xffffffffu, p, 1);
        p += __shfl_xor_sync(0xffffffffu, p, 2);
        p += __shfl_xor_sync(0xffffffffu, p, 4);
        float w = __expf(p);
        acc.x += w * gcur.x;
        acc.y += w * gcur.y;
        acc.z += w * gcur.z;
        acc.w += w * gcur.w;
        den += w;

        gcur = gnext;
        gnext = gnn;
    }

    const float inv = 1.f / den;
    const float4 b = reinterpret_cast<const float4*>(bias)[lane];
    float v0 = acc.x * inv + b.x; v0 = (v0 > 0.f) ? v0 : expm1f(v0);
    float v1 = acc.y * inv + b.y; v1 = (v1 > 0.f) ? v1 : expm1f(v1);
    float v2 = acc.z * inv + b.z; v2 = (v2 > 0.f) ? v2 : expm1f(v2);
    float v3 = acc.w * inv + b.w; v3 = (v3 > 0.f) ? v3 : expm1f(v3);
    reinterpret_cast<float4*>(g_h1)[d * 32 + lane] = make_float4(v0, v1, v2, v3);
}

// ---------------- layer 2: aggregation, 4 dsts per warp (8 lanes / dst) -------------
__global__ __launch_bounds__(256) void agg2_kernel(const float* __restrict__ att,
                                                   const float* __restrict__ bias,
                                                   float* __restrict__ out) {
    const int lane = threadIdx.x & 31;
    const int grp  = lane >> 3;
    const int lg   = lane & 7;
    const int wid  = blockIdx.x * (blockDim.x >> 5) + (threadIdx.x >> 5);
    int d = wid * 4 + grp;
    const bool dvalid = (d < NN);
    if (d >= NN) d = NN - 1;

    const float4* __restrict__ gl4 = reinterpret_cast<const float4*>(g_gl2);
    const float4 grd  = reinterpret_cast<const float4*>(g_gr2)[d * 8 + lg];
    const float4 at   = reinterpret_cast<const float4*>(att)[lg];

    const unsigned start = g_rowstart[d];
    const unsigned deg   = dvalid ? (g_rowstart[d + 1] - start) : 0u;

    unsigned mdeg = deg;
#pragma unroll
    for (int off = 8; off < 32; off <<= 1) {
        unsigned o = __shfl_xor_sync(0xffffffffu, mdeg, off);
        mdeg = (o > mdeg) ? o : mdeg;
    }

    float4 acc = make_float4(0.f, 0.f, 0.f, 0.f);
    float  den = 0.f;

    int snext = (deg > 0) ? g_csrc[start] : d;
    float4 g = gl4[d * 8 + lg];

    for (unsigned j = 0; j <= mdeg; ++j) {
        float4 gc = g;
        int snn = (j + 2 <= deg) ? g_csrc[start + j + 1] : d;
        g = gl4[snext * 8 + lg];
        snext = snn;

        float m0 = gc.x + grd.x; m0 = (m0 > 0.f) ? m0 : NEG * m0;
        float m1 = gc.y + grd.y; m1 = (m1 > 0.f) ? m1 : NEG * m1;
        float m2 = gc.z + grd.z; m2 = (m2 > 0.f) ? m2 : NEG * m2;
        float m3 = gc.w + grd.w; m3 = (m3 > 0.f) ? m3 : NEG * m3;
        float p = at.x * m0 + at.y * m1 + at.z * m2 + at.w * m3;
        p += __shfl_xor_sync(0xffffffffu, p, 1);
        p += __shfl_xor_sync(0xffffffffu, p, 2);
        p += __shfl_xor_sync(0xffffffffu, p, 4);
        float w = (j <= deg) ? __expf(p) : 0.f;
        acc.x += w * gc.x;
        acc.y += w * gc.y;
        acc.z += w * gc.z;
        acc.w += w * gc.w;
        den += w;
    }

    if (dvalid) {
        const float inv = 1.f / den;
        const float4 b = reinterpret_cast<const float4*>(bias)[lg];
        reinterpret_cast<float4*>(out)[d * 8 + lg] =
            make_float4(acc.x * inv + b.x, acc.y * inv + b.y,
                        acc.z * inv + b.z, acc.w * inv + b.w);
    }
}

// ---------------- launch ----------------
extern "C" void kernel_launch(void* const* d_in, const int* in_sizes, int n_in,
                              void* d_out, int out_size) {
    const float* x    = (const float*)d_in[0];
    const int*   ei   = (const int*)d_in[1];
    const float* Wl1  = (const float*)d_in[2];
    const float* bl1  = (const float*)d_in[3];
    const float* Wr1  = (const float*)d_in[4];
    const float* br1  = (const float*)d_in[5];
    const float* att1 = (const float*)d_in[6];
    const float* bias1= (const float*)d_in[7];
    const float* Wl2  = (const float*)d_in[8];
    const float* bl2  = (const float*)d_in[9];
    const float* Wr2  = (const float*)d_in[10];
    const float* br2  = (const float*)d_in[11];
    const float* att2 = (const float*)d_in[12];
    const float* bias2= (const float*)d_in[13];
    float* out = (float*)d_out;

    // gemm1: A half 128*17*16 = 34816 + W 128*16*16 = 32768 -> 67584 (3 blocks/SM)
    // gemm2: M=32, MBLK=32, CT=4, RB=128 -> 128*33*16 + 128*32*4 = 83968
    const int smem1 = 128 * 17 * 16 + 128 * 16 * 16;
    const int smem2 = 128 * 33 * 16 + 128 * 32 * 4;
    cudaFuncSetAttribute(gemm1_hist_kernel,
                         cudaFuncAttributeMaxDynamicSharedMemorySize, smem1);
    cudaFuncSetAttribute((gemm_kernel<32, 32, 4, 128>),
                         cudaFuncAttributeMaxDynamicSharedMemorySize, smem2);

    float *gl1p, *gr1p, *h1p, *gl2p, *gr2p;
    cudaGetSymbolAddress((void**)&gl1p, g_gl1);
    cudaGetSymbolAddress((void**)&gr1p, g_gr1);
    cudaGetSymbolAddress((void**)&h1p,  g_h1);
    cudaGetSymbolAddress((void**)&gl2p, g_gl2);
    cudaGetSymbolAddress((void**)&gr2p, g_gr2);

    // slot 1: gemm1 + fused hist; slots 2-3: scan/fill; slot 4: agg1 (PROFILED)
    gemm1_hist_kernel<<<dim3((NN + 127) / 128, 5), 256, smem1>>>(
        x, NN, Wl1, bl1, gl1p, Wr1, br1, gr1p, ei);
    csr_scan_kernel<<<1, 1024>>>();
    csr_fill_kernel<<<(EE + 255) / 256, 256>>>(ei);

    agg1_kernel<<<(NN + 7) / 8, 256>>>(att1, bias1);

    gemm_kernel<32, 32, 4, 128><<<dim3((NN + 127) / 128, 2), 256, smem2>>>(
        h1p, NN, Wl2, bl2, gl2p, Wr2, br2, gr2p);
    agg2_kernel<<<(NN + 31) / 32, 256>>>(att2, bias2, out);
}

// round 14
// speedup vs baseline: 1.3222x; 1.1007x over previous
#include <cuda_runtime.h>
#include <cuda_bf16.h>
#include <cstdint>

#define NN 50000
#define EE 800000
#define NEG 0.2f

typedef unsigned long long u64;

// ---------------- scratch (static device globals; no allocation) ----------------
__device__ __align__(16) float    g_gl1[NN * 128];
__device__ __align__(16) float    g_gr1[NN * 128];
__device__ __align__(16) float    g_h1 [NN * 128];
__device__ __align__(16) float    g_gl2[NN * 32];
__device__ __align__(16) float    g_gr2[NN * 32];
// bf16-split staging for the tensor-core layer-1 GEMM
__device__ __align__(16) __nv_bfloat16 g_xhi[NN * 128];
__device__ __align__(16) __nv_bfloat16 g_xlo[NN * 128];
__device__ __align__(16) __nv_bfloat16 g_wthi[2 * 128 * 128];  // W^T (n-major) per mat
__device__ __align__(16) __nv_bfloat16 g_wtlo[2 * 128 * 128];
// CSR by dst
__device__ unsigned g_cnt[NN];          // statically zero; scan re-zeroes each call
__device__ unsigned g_rowstart[NN + 1];
__device__ unsigned g_cursor[NN];
__device__ int      g_csrc[EE];

// ---------------- f32x2 helpers (layer-2 scalar GEMM) ----------------
__device__ __forceinline__ u64 pack2(float lo, float hi) {
    u64 r;
    asm("mov.b64 %0, {%1, %2};" : "=l"(r) : "f"(lo), "f"(hi));
    return r;
}
__device__ __forceinline__ float2 unpack2(u64 v) {
    float2 r;
    asm("mov.b64 {%0, %1}, %2;" : "=f"(r.x), "=f"(r.y) : "l"(v));
    return r;
}
__device__ __forceinline__ void ffma2(u64& d, u64 a, u64 b) {
    asm("fma.rn.f32x2 %0, %1, %2, %0;" : "+l"(d) : "l"(a), "l"(b));
}

// ---------------- warp-MMA helpers (base-target: sm_80+, compiles for sm_103) -------
__device__ __forceinline__ uint32_t smem_u32(const void* p) {
    uint32_t a;
    asm("{ .reg .u64 t; cvta.to.shared.u64 t, %1; cvt.u32.u64 %0, t; }"
        : "=r"(a) : "l"(p));
    return a;
}
__device__ __forceinline__ void ldm_x4(uint32_t a[4], uint32_t addr) {
    asm volatile("ldmatrix.sync.aligned.m8n8.x4.shared.b16 {%0,%1,%2,%3}, [%4];"
        : "=r"(a[0]), "=r"(a[1]), "=r"(a[2]), "=r"(a[3]) : "r"(addr));
}
__device__ __forceinline__ void ldm_x2(uint32_t b[2], uint32_t addr) {
    asm volatile("ldmatrix.sync.aligned.m8n8.x2.shared.b16 {%0,%1}, [%2];"
        : "=r"(b[0]), "=r"(b[1]) : "r"(addr));
}
__device__ __forceinline__ void mma_bf16(float c[4], const uint32_t a[4],
                                         const uint32_t b[2]) {
    asm volatile(
        "mma.sync.aligned.m16n8k16.row.col.f32.bf16.bf16.f32 "
        "{%0,%1,%2,%3}, {%4,%5,%6,%7}, {%8,%9}, {%0,%1,%2,%3};"
        : "+f"(c[0]), "+f"(c[1]), "+f"(c[2]), "+f"(c[3])
        : "r"(a[0]), "r"(a[1]), "r"(a[2]), "r"(a[3]), "r"(b[0]), "r"(b[1]));
}

// ---------------- prep: fp32 -> bf16 hi/lo split ----------------
__global__ void convert_x_kernel(const float* __restrict__ x) {
    int i = blockIdx.x * blockDim.x + threadIdx.x;       // 4 elems per thread
    if (i >= NN * 32) return;
    float4 v = reinterpret_cast<const float4*>(x)[i];
    __nv_bfloat16 h0 = __float2bfloat16(v.x), h1 = __float2bfloat16(v.y);
    __nv_bfloat16 h2 = __float2bfloat16(v.z), h3 = __float2bfloat16(v.w);
    __nv_bfloat16 l0 = __float2bfloat16(v.x - __bfloat162float(h0));
    __nv_bfloat16 l1 = __float2bfloat16(v.y - __bfloat162float(h1));
    __nv_bfloat16 l2 = __float2bfloat16(v.z - __bfloat162float(h2));
    __nv_bfloat16 l3 = __float2bfloat16(v.w - __bfloat162float(h3));
    uint2 hw, lw;
    hw.x = (uint32_t)__bfloat16_as_ushort(h0) | ((uint32_t)__bfloat16_as_ushort(h1) << 16);
    hw.y = (uint32_t)__bfloat16_as_ushort(h2) | ((uint32_t)__bfloat16_as_ushort(h3) << 16);
    lw.x = (uint32_t)__bfloat16_as_ushort(l0) | ((uint32_t)__bfloat16_as_ushort(l1) << 16);
    lw.y = (uint32_t)__bfloat16_as_ushort(l2) | ((uint32_t)__bfloat16_as_ushort(l3) << 16);
    reinterpret_cast<uint2*>(g_xhi)[i] = hw;
    reinterpret_cast<uint2*>(g_xlo)[i] = lw;
}
__global__ void convert_w_kernel(const float* __restrict__ Wl, const float* __restrict__ Wr) {
    int i = blockIdx.x * blockDim.x + threadIdx.x;       // over 2*128*128
    if (i >= 2 * 128 * 128) return;
    int mat = i >> 14;
    int r   = i & 16383;
    int nn  = r >> 7;
    int k   = r & 127;
    float v = (mat ? Wr : Wl)[k * 128 + nn];             // W^T[n][k] = W[k][n]
    __nv_bfloat16 h = __float2bfloat16(v);
    __nv_bfloat16 l = __float2bfloat16(v - __bfloat162float(h));
    g_wthi[i] = h;
    g_wtlo[i] = l;
}

// ---------------- layer-1 GEMM via mma.sync bf16-split -----------------------------
// grid (391, 2): 128 rows x 128 cols of mat = blockIdx.y. 256 threads (8 warps).
// Warp tile 64x32: wr = wid>>2 picks row half, wc = wid&3 picks 32-col strip.
// SMEM: Ahi, Alo, BThi, BTlo tiles, 128 rows x 128 bf16, pitch 272B (conflict-free).
__global__ __launch_bounds__(256) void gemm1_mma_kernel(
    int n, const float* __restrict__ bl, const float* __restrict__ br)
{
    constexpr int PITCH   = 272;                 // bytes per row (17 x 16B)
    constexpr int TILE_B  = 128 * PITCH;         // 34816
    constexpr int OFF_AHI = 0;
    constexpr int OFF_ALO = TILE_B;
    constexpr int OFF_BHI = 2 * TILE_B;
    constexpr int OFF_BLO = 3 * TILE_B;

    extern __shared__ char sm[];
    const uint32_t sbase = smem_u32(sm);
    const int tid  = threadIdx.x;
    const int wid  = tid >> 5;
    const int lane = tid & 31;
    const int mat  = blockIdx.y;
    const int row0 = blockIdx.x * 128;

    // fill A tiles (hi, lo): 128 rows x 16 uint4, coalesced reads
    {
        const uint4* xh = reinterpret_cast<const uint4*>(g_xhi);
        const uint4* xl = reinterpret_cast<const uint4*>(g_xlo);
        for (int i = tid; i < 128 * 16; i += 256) {
            int r = i >> 4, c = i & 15;
            int gr = row0 + r;
            if (gr >= n) gr = n - 1;
            *reinterpret_cast<uint4*>(sm + OFF_AHI + r * PITCH + c * 16) = xh[gr * 16 + c];
            *reinterpret_cast<uint4*>(sm + OFF_ALO + r * PITCH + c * 16) = xl[gr * 16 + c];
        }
        // one matrix = 128*128 bf16 = 32768 B = 2048 uint4  (round-13 bug: was *1024)
        const uint4* wh = reinterpret_cast<const uint4*>(g_wthi) + mat * 2048;
        const uint4* wl = reinterpret_cast<const uint4*>(g_wtlo) + mat * 2048;
        for (int i = tid; i < 128 * 16; i += 256) {
            int r = i >> 4, c = i & 15;
            *reinterpret_cast<uint4*>(sm + OFF_BHI + r * PITCH + c * 16) = wh[r * 16 + c];
            *reinterpret_cast<uint4*>(sm + OFF_BLO + r * PITCH + c * 16) = wl[r * 16 + c];
        }
    }
    __syncthreads();

    const int mbase = (wid >> 2) * 64;
    const int nbase = (wid & 3) * 32;

    float acc[4][4][4];
#pragma unroll
    for (int mt = 0; mt < 4; mt++)
#pragma unroll
        for (int nt = 0; nt < 4; nt++)
#pragma unroll
            for (int q = 0; q < 4; q++) acc[mt][nt][q] = 0.f;

    // ldmatrix per-lane addressing
    const int arow  = lane & 15;
    const int akoff = (lane >> 4) << 4;          // bytes (+16 for k 8-15)
    const int brow  = lane & 7;
    const int bkoff = ((lane >> 3) & 1) << 4;

    for (int ks = 0; ks < 8; ++ks) {
        const int kb = ks * 32;                  // 16 bf16 = 32 bytes
        uint32_t ah[4][4], al[4][4];
#pragma unroll
        for (int mt = 0; mt < 4; mt++) {
            uint32_t addr = sbase + OFF_AHI + (mbase + mt * 16 + arow) * PITCH + kb + akoff;
            ldm_x4(ah[mt], addr);
            ldm_x4(al[mt], addr + (OFF_ALO - OFF_AHI));
        }
        uint32_t bh[4][2], bo[4][2];
#pragma unroll
        for (int nt = 0; nt < 4; nt++) {
            uint32_t addr = sbase + OFF_BHI + (nbase + nt * 8 + brow) * PITCH + kb + bkoff;
            ldm_x2(bh[nt], addr);
            ldm_x2(bo[nt], addr + (OFF_BLO - OFF_BHI));
        }
#pragma unroll
        for (int mt = 0; mt < 4; mt++) {
#pragma unroll
            for (int nt = 0; nt < 4; nt++) {
                mma_bf16(acc[mt][nt], ah[mt], bh[nt]);   // hi*hi
                mma_bf16(acc[mt][nt], ah[mt], bo[nt]);   // hi*lo
                mma_bf16(acc[mt][nt], al[mt], bh[nt]);   // lo*hi
            }
        }
    }

    // epilogue: c0,c1 -> (row t/4, col 2*(t%4)+{0,1}); c2,c3 -> row+8
    const float* __restrict__ b = mat ? br : bl;
    float* __restrict__ C = mat ? g_gr1 : g_gl1;
    const int rql = lane >> 2;
    const int cql = (lane & 3) * 2;
#pragma unroll
    for (int mt = 0; mt < 4; mt++) {
        int r0 = row0 + mbase + mt * 16 + rql;
        int r1 = r0 + 8;
#pragma unroll
        for (int nt = 0; nt < 4; nt++) {
            int col = nbase + nt * 8 + cql;
            float2 bv = *reinterpret_cast<const float2*>(b + col);
            if (r0 < n) {
                float2 v = make_float2(acc[mt][nt][0] + bv.x, acc[mt][nt][1] + bv.y);
                *reinterpret_cast<float2*>(C + r0 * 128 + col) = v;
            }
            if (r1 < n) {
                float2 v = make_float2(acc[mt][nt][2] + bv.x, acc[mt][nt][3] + bv.y);
                *reinterpret_cast<float2*>(C + r1 * 128 + col) = v;
            }
        }
    }
}

// ---------------- CSR build ----------------
__global__ void csr_hist_kernel(const int* __restrict__ ei) {
    int i = blockIdx.x * blockDim.x + threadIdx.x;
    if (i < EE) atomicAdd(&g_cnt[ei[EE + i]], 1u);
}
__global__ __launch_bounds__(1024) void csr_scan_kernel() {
    __shared__ unsigned s[1024];
    const int T = 1024;
    const int CH = (NN + T - 1) / T;
    int t = threadIdx.x;
    int base = t * CH;
    unsigned sum = 0;
    for (int i = 0; i < CH; i++) {
        int j = base + i;
        if (j < NN) sum += g_cnt[j];
    }
    s[t] = sum;
    __syncthreads();
    for (int off = 1; off < T; off <<= 1) {
        unsigned u = (t >= off) ? s[t - off] : 0u;
        __syncthreads();
        s[t] += u;
        __syncthreads();
    }
    unsigned run = s[t] - sum;
    for (int i = 0; i < CH; i++) {
        int j = base + i;
        if (j < NN) {
            unsigned c = g_cnt[j];
            g_cnt[j] = 0u;
            g_rowstart[j] = run;
            g_cursor[j]   = run;
            run += c;
        }
    }
    if (t == T - 1) g_rowstart[NN] = run;
}
__global__ void csr_fill_kernel(const int* __restrict__ ei) {
    int i = blockIdx.x * blockDim.x + threadIdx.x;
    if (i < EE) {
        int d = ei[EE + i];
        unsigned pos = atomicAdd(&g_cursor[d], 1u);
        g_csrc[pos] = ei[i];
    }
}

// ---------------- layer-2 GEMM (scalar f32x2) ----------------
template <int M, int MBLK, int CT, int RB>
__global__ __launch_bounds__(256) void gemm_kernel(
    const float* __restrict__ A, int n,
    const float* __restrict__ W1, const float* __restrict__ b1, float* __restrict__ C1,
    const float* __restrict__ W2, const float* __restrict__ b2, float* __restrict__ C2)
{
    constexpr int K    = 128;
    constexpr int TXN  = MBLK / CT;
    constexpr int TYN  = 256 / TXN;
    constexpr int RT   = RB / TYN;
    constexpr int CP   = CT / 2;
    constexpr int NCH  = CT / 4;
    constexpr int NH   = M / MBLK;
    constexpr int AP   = 33;

    extern __shared__ float smf[];
    float4* As4 = reinterpret_cast<float4*>(smf);
    float4* Ws4 = reinterpret_cast<float4*>(smf) + RB * AP;

    const int mat  = blockIdx.y / NH;
    const int col0 = (blockIdx.y % NH) * MBLK;
    const float* __restrict__ W = mat ? W2 : W1;
    const float* __restrict__ b = mat ? b2 : b1;
    float* __restrict__       C = mat ? C2 : C1;

    const int tid  = threadIdx.x;
    const int row0 = blockIdx.x * RB;

    for (int i = tid; i < RB * 32; i += 256) {
        int r  = i >> 5;
        int c4 = i & 31;
        int gr_ = row0 + r;
        float4 v = make_float4(0.f, 0.f, 0.f, 0.f);
        if (gr_ < n) v = reinterpret_cast<const float4*>(A)[gr_ * 32 + c4];
        As4[r * AP + c4] = v;
    }
    for (int i = tid; i < K * (MBLK / 4); i += 256) {
        int k  = i / (MBLK / 4);
        int c4 = i % (MBLK / 4);
        int c  = c4 * 4;
        int txg   = c / CT;
        int chunk = (c % CT) >> 2;
        float4 v = reinterpret_cast<const float4*>(W + k * M + col0)[c4];
        Ws4[(k * NCH + chunk) * TXN + txg] = v;
    }
    __syncthreads();

    const int tx = tid % TXN;
    const int ty = tid / TXN;

    u64 acc[RT][CP];
    const u64 zz = pack2(0.f, 0.f);
#pragma unroll
    for (int i = 0; i < RT; i++)
#pragma unroll
        for (int j = 0; j < CP; j++) acc[i][j] = zz;

#pragma unroll 4
    for (int k4 = 0; k4 < K / 4; ++k4) {
        float4 av[RT];
#pragma unroll
        for (int i = 0; i < RT; i++)
            av[i] = As4[(ty + i * TYN) * AP + k4];

#pragma unroll
        for (int kk = 0; kk < 4; ++kk) {
            u64 wv[CP];
            const ulonglong2* wp = reinterpret_cast<const ulonglong2*>(
                Ws4 + (k4 * 4 + kk) * NCH * TXN);
#pragma unroll
            for (int jc = 0; jc < NCH; ++jc) {
                ulonglong2 u = wp[jc * TXN + tx];
                wv[jc * 2] = u.x;
                if constexpr (CP > 1) wv[jc * 2 + 1] = u.y;
            }
#pragma unroll
            for (int i = 0; i < RT; i++) {
                float a = (kk == 0) ? av[i].x : (kk == 1) ? av[i].y
                        : (kk == 2) ? av[i].z : av[i].w;
                u64 ap = pack2(a, a);
#pragma unroll
                for (int j = 0; j < CP; j++) ffma2(acc[i][j], ap, wv[j]);
            }
        }
    }

#pragma unroll
    for (int i = 0; i < RT; i++) {
        int r = row0 + ty + i * TYN;
        if (r < n) {
#pragma unroll
            for (int j = 0; j < CP; j++) {
                int c = col0 + tx * CT + j * 2;
                float2 v = unpack2(acc[i][j]);
                C[r * M + c]     = v.x + b[c];
                C[r * M + c + 1] = v.y + b[c + 1];
            }
        }
    }
}

// ---------------- layer 1: fused attention aggregation (warp per dst, depth-2) -------
__global__ __launch_bounds__(256) void agg1_kernel(const float* __restrict__ att,
                                                   const float* __restrict__ bias) {
    const int lane = threadIdx.x & 31;
    const int d = blockIdx.x * (blockDim.x >> 5) + (threadIdx.x >> 5);
    if (d >= NN) return;

    const float4* __restrict__ gl4 = reinterpret_cast<const float4*>(g_gl1);
    const float4  grd = reinterpret_cast<const float4*>(g_gr1)[d * 32 + lane];
    const float4  at  = reinterpret_cast<const float4*>(att)[lane];

    float4 acc = make_float4(0.f, 0.f, 0.f, 0.f);
    float  den = 0.f;

    const unsigned start = g_rowstart[d];
    const unsigned deg   = g_rowstart[d + 1] - start;

    int s1 = (deg > 0) ? g_csrc[start]     : d;
    int s2 = (deg > 1) ? g_csrc[start + 1] : d;
    float4 gcur  = gl4[d  * 32 + lane];
    float4 gnext = gl4[s1 * 32 + lane];

    for (unsigned j = 0; j <= deg; ++j) {
        float4 gnn = gl4[s2 * 32 + lane];
        s2 = (j + 3 <= deg) ? g_csrc[start + j + 2] : d;

        float m0 = gcur.x + grd.x; m0 = (m0 > 0.f) ? m0 : NEG * m0;
        float m1 = gcur.y + grd.y; m1 = (m1 > 0.f) ? m1 : NEG * m1;
        float m2 = gcur.z + grd.z; m2 = (m2 > 0.f) ? m2 : NEG * m2;
        float m3 = gcur.w + grd.w; m3 = (m3 > 0.f) ? m3 : NEG * m3;
        float p = at.x * m0 + at.y * m1 + at.z * m2 + at.w * m3;
        p += __shfl_xor_sync(0xffffffffu, p, 1);
        p += __shfl_xor_sync(0xffffffffu, p, 2);
        p += __shfl_xor_sync(0xffffffffu, p, 4);
        float w = __expf(p);
        acc.x += w * gcur.x;
        acc.y += w * gcur.y;
        acc.z += w * gcur.z;
        acc.w += w * gcur.w;
        den += w;

        gcur = gnext;
        gnext = gnn;
    }

    const float inv = 1.f / den;
    const float4 b = reinterpret_cast<const float4*>(bias)[lane];
    float v0 = acc.x * inv + b.x; v0 = (v0 > 0.f) ? v0 : expm1f(v0);
    float v1 = acc.y * inv + b.y; v1 = (v1 > 0.f) ? v1 : expm1f(v1);
    float v2 = acc.z * inv + b.z; v2 = (v2 > 0.f) ? v2 : expm1f(v2);
    float v3 = acc.w * inv + b.w; v3 = (v3 > 0.f) ? v3 : expm1f(v3);
    reinterpret_cast<float4*>(g_h1)[d * 32 + lane] = make_float4(v0, v1, v2, v3);
}

// ---------------- layer 2: aggregation, 4 dsts per warp (8 lanes / dst) -------------
__global__ __launch_bounds__(256) void agg2_kernel(const float* __restrict__ att,
                                                   const float* __restrict__ bias,
                                                   float* __restrict__ out) {
    const int lane = threadIdx.x & 31;
    const int grp  = lane >> 3;
    const int lg   = lane & 7;
    const int wid  = blockIdx.x * (blockDim.x >> 5) + (threadIdx.x >> 5);
    int d = wid * 4 + grp;
    const bool dvalid = (d < NN);
    if (d >= NN) d = NN - 1;

    const float4* __restrict__ gl4 = reinterpret_cast<const float4*>(g_gl2);
    const float4 grd  = reinterpret_cast<const float4*>(g_gr2)[d * 8 + lg];
    const float4 at   = reinterpret_cast<const float4*>(att)[lg];

    const unsigned start = g_rowstart[d];
    const unsigned deg   = dvalid ? (g_rowstart[d + 1] - start) : 0u;

    unsigned mdeg = deg;
#pragma unroll
    for (int off = 8; off < 32; off <<= 1) {
        unsigned o = __shfl_xor_sync(0xffffffffu, mdeg, off);
        mdeg = (o > mdeg) ? o : mdeg;
    }

    float4 acc = make_float4(0.f, 0.f, 0.f, 0.f);
    float  den = 0.f;

    int snext = (deg > 0) ? g_csrc[start] : d;
    float4 g = gl4[d * 8 + lg];

    for (unsigned j = 0; j <= mdeg; ++j) {
        float4 gc = g;
        int snn = (j + 2 <= deg) ? g_csrc[start + j + 1] : d;
        g = gl4[snext * 8 + lg];
        snext = snn;

        float m0 = gc.x + grd.x; m0 = (m0 > 0.f) ? m0 : NEG * m0;
        float m1 = gc.y + grd.y; m1 = (m1 > 0.f) ? m1 : NEG * m1;
        float m2 = gc.z + grd.z; m2 = (m2 > 0.f) ? m2 : NEG * m2;
        float m3 = gc.w + grd.w; m3 = (m3 > 0.f) ? m3 : NEG * m3;
        float p = at.x * m0 + at.y * m1 + at.z * m2 + at.w * m3;
        p += __shfl_xor_sync(0xffffffffu, p, 1);
        p += __shfl_xor_sync(0xffffffffu, p, 2);
        p += __shfl_xor_sync(0xffffffffu, p, 4);
        float w = (j <= deg) ? __expf(p) : 0.f;
        acc.x += w * gc.x;
        acc.y += w * gc.y;
        acc.z += w * gc.z;
        acc.w += w * gc.w;
        den += w;
    }

    if (dvalid) {
        const float inv = 1.f / den;
        const float4 b = reinterpret_cast<const float4*>(bias)[lg];
        reinterpret_cast<float4*>(out)[d * 8 + lg] =
            make_float4(acc.x * inv + b.x, acc.y * inv + b.y,
                        acc.z * inv + b.z, acc.w * inv + b.w);
    }
}

// ---------------- launch ----------------
extern "C" void kernel_launch(void* const* d_in, const int* in_sizes, int n_in,
                              void* d_out, int out_size) {
    const float* x    = (const float*)d_in[0];
    const int*   ei   = (const int*)d_in[1];
    const float* Wl1  = (const float*)d_in[2];
    const float* bl1  = (const float*)d_in[3];
    const float* Wr1  = (const float*)d_in[4];
    const float* br1  = (const float*)d_in[5];
    const float* att1 = (const float*)d_in[6];
    const float* bias1= (const float*)d_in[7];
    const float* Wl2  = (const float*)d_in[8];
    const float* bl2  = (const float*)d_in[9];
    const float* Wr2  = (const float*)d_in[10];
    const float* br2  = (const float*)d_in[11];
    const float* att2 = (const float*)d_in[12];
    const float* bias2= (const float*)d_in[13];
    float* out = (float*)d_out;

    const int smem_mma = 4 * 128 * 272;            // 139264
    const int smem2    = 128 * 33 * 16 + 128 * 32 * 4;
    cudaFuncSetAttribute(gemm1_mma_kernel,
                         cudaFuncAttributeMaxDynamicSharedMemorySize, smem_mma);
    cudaFuncSetAttribute((gemm_kernel<32, 32, 4, 128>),
                         cudaFuncAttributeMaxDynamicSharedMemorySize, smem2);

    float *h1p, *gl2p, *gr2p;
    cudaGetSymbolAddress((void**)&h1p,  g_h1);
    cudaGetSymbolAddress((void**)&gl2p, g_gl2);
    cudaGetSymbolAddress((void**)&gr2p, g_gr2);

    // slots 1-3: converts + hist; slot 4: gemm1_mma (PROFILED — expect tensor pipe > 0)
    convert_x_kernel<<<(NN * 32 + 255) / 256, 256>>>(x);
    convert_w_kernel<<<(2 * 128 * 128 + 255) / 256, 256>>>(Wl1, Wr1);
    csr_hist_kernel<<<(EE + 255) / 256, 256>>>(ei);
    gemm1_mma_kernel<<<dim3((NN + 127) / 128, 2), 256, smem_mma>>>(NN, bl1, br1);
    csr_scan_kernel<<<1, 1024>>>();
    csr_fill_kernel<<<(EE + 255) / 256, 256>>>(ei);

    agg1_kernel<<<(NN + 7) / 8, 256>>>(att1, bias1);

    gemm_kernel<32, 32, 4, 128><<<dim3((NN + 127) / 128, 2), 256, smem2>>>(
        h1p, NN, Wl2, bl2, gl2p, Wr2, br2, gr2p);
    agg2_kernel<<<(NN + 31) / 32, 256>>>(att2, bias2, out);
}

// round 15
// speedup vs baseline: 1.4658x; 1.1086x over previous
#include <cuda_runtime.h>
#include <cuda_bf16.h>
#include <cstdint>

#define NN 50000
#define EE 800000
#define NEG 0.2f

typedef unsigned long long u64;

// ---------------- scratch (static device globals; no allocation) ----------------
__device__ __align__(16) float    g_gl1[NN * 128];
__device__ __align__(16) float    g_gr1[NN * 128];
__device__ __align__(16) float    g_gl2[NN * 32];
__device__ __align__(16) float    g_gr2[NN * 32];
// bf16-split staging for the tensor-core GEMMs
__device__ __align__(16) __nv_bfloat16 g_xhi[NN * 128];
__device__ __align__(16) __nv_bfloat16 g_xlo[NN * 128];
__device__ __align__(16) __nv_bfloat16 g_h1hi[NN * 128];   // elu(h1) split (from agg1)
__device__ __align__(16) __nv_bfloat16 g_h1lo[NN * 128];
__device__ __align__(16) __nv_bfloat16 g_wthi[2 * 128 * 128];  // layer1 W^T per mat
__device__ __align__(16) __nv_bfloat16 g_wtlo[2 * 128 * 128];
__device__ __align__(16) __nv_bfloat16 g_wt2hi[2 * 32 * 128];  // layer2 W^T per mat
__device__ __align__(16) __nv_bfloat16 g_wt2lo[2 * 32 * 128];
// CSR by dst
__device__ unsigned g_cnt[NN];          // statically zero; scan re-zeroes each call
__device__ unsigned g_rowstart[NN + 1];
__device__ unsigned g_cursor[NN];
__device__ int      g_csrc[EE];

// ---------------- warp-MMA helpers (base-target: sm_80+, compiles for sm_103) -------
__device__ __forceinline__ uint32_t smem_u32(const void* p) {
    uint32_t a;
    asm("{ .reg .u64 t; cvta.to.shared.u64 t, %1; cvt.u32.u64 %0, t; }"
        : "=r"(a) : "l"(p));
    return a;
}
__device__ __forceinline__ void ldm_x4(uint32_t a[4], uint32_t addr) {
    asm volatile("ldmatrix.sync.aligned.m8n8.x4.shared.b16 {%0,%1,%2,%3}, [%4];"
        : "=r"(a[0]), "=r"(a[1]), "=r"(a[2]), "=r"(a[3]) : "r"(addr));
}
__device__ __forceinline__ void ldm_x2(uint32_t b[2], uint32_t addr) {
    asm volatile("ldmatrix.sync.aligned.m8n8.x2.shared.b16 {%0,%1}, [%2];"
        : "=r"(b[0]), "=r"(b[1]) : "r"(addr));
}
__device__ __forceinline__ void mma_bf16(float c[4], const uint32_t a[4],
                                         const uint32_t b[2]) {
    asm volatile(
        "mma.sync.aligned.m16n8k16.row.col.f32.bf16.bf16.f32 "
        "{%0,%1,%2,%3}, {%4,%5,%6,%7}, {%8,%9}, {%0,%1,%2,%3};"
        : "+f"(c[0]), "+f"(c[1]), "+f"(c[2]), "+f"(c[3])
        : "r"(a[0]), "r"(a[1]), "r"(a[2]), "r"(a[3]), "r"(b[0]), "r"(b[1]));
}
__device__ __forceinline__ uint32_t pack_bf2(float a, float b) {
    return (uint32_t)__bfloat16_as_ushort(__float2bfloat16(a))
         | ((uint32_t)__bfloat16_as_ushort(__float2bfloat16(b)) << 16);
}

// ---------------- prep: fp32 -> bf16 hi/lo split ----------------
__global__ void convert_x_kernel(const float* __restrict__ x) {
    int i = blockIdx.x * blockDim.x + threadIdx.x;       // 4 elems per thread
    if (i >= NN * 32) return;
    float4 v = reinterpret_cast<const float4*>(x)[i];
    float h0 = __bfloat162float(__float2bfloat16(v.x));
    float h1 = __bfloat162float(__float2bfloat16(v.y));
    float h2 = __bfloat162float(__float2bfloat16(v.z));
    float h3 = __bfloat162float(__float2bfloat16(v.w));
    uint2 hw, lw;
    hw.x = pack_bf2(v.x, v.y);
    hw.y = pack_bf2(v.z, v.w);
    lw.x = pack_bf2(v.x - h0, v.y - h1);
    lw.y = pack_bf2(v.z - h2, v.w - h3);
    reinterpret_cast<uint2*>(g_xhi)[i] = hw;
    reinterpret_cast<uint2*>(g_xlo)[i] = lw;
}
// converts layer-1 W^T (2*128*128) AND layer-2 W^T (2*32*128) in one launch
__global__ void convert_w_kernel(const float* __restrict__ Wl1f,
                                 const float* __restrict__ Wr1f,
                                 const float* __restrict__ Wl2f,
                                 const float* __restrict__ Wr2f) {
    int i = blockIdx.x * blockDim.x + threadIdx.x;
    if (i < 2 * 128 * 128) {
        int mat = i >> 14;
        int r   = i & 16383;
        int nn  = r >> 7;
        int k   = r & 127;
        float v = (mat ? Wr1f : Wl1f)[k * 128 + nn];
        float h = __bfloat162float(__float2bfloat16(v));
        g_wthi[i] = __float2bfloat16(v);
        g_wtlo[i] = __float2bfloat16(v - h);
    } else if (i < 2 * 128 * 128 + 2 * 32 * 128) {
        int j   = i - 2 * 128 * 128;
        int mat = j >> 12;                 // 4096 per matrix
        int r   = j & 4095;
        int nn  = r >> 7;
        int k   = r & 127;
        float v = (mat ? Wr2f : Wl2f)[k * 32 + nn];
        float h = __bfloat162float(__float2bfloat16(v));
        g_wt2hi[j] = __float2bfloat16(v);
        g_wt2lo[j] = __float2bfloat16(v - h);
    }
}

// ---------------- layer-1 GEMM via mma.sync bf16-split (RB=64 -> 2 blocks/SM) -------
// grid (782, 2): 64 rows x 128 cols of mat = blockIdx.y. 256 threads (8 warps).
// Warp tile 32x32: wid>>2 picks 32-row group, wid&3 picks 32-col strip.
__global__ __launch_bounds__(256) void gemm1_mma_kernel(
    int n, const float* __restrict__ bl, const float* __restrict__ br)
{
    constexpr int PITCH   = 272;                 // bytes per row (17 x 16B)
    constexpr int A_TILE  = 64 * PITCH;          // 17408
    constexpr int B_TILE  = 128 * PITCH;         // 34816
    constexpr int OFF_AHI = 0;
    constexpr int OFF_ALO = A_TILE;
    constexpr int OFF_BHI = 2 * A_TILE;
    constexpr int OFF_BLO = 2 * A_TILE + B_TILE;

    extern __shared__ char sm[];
    const uint32_t sbase = smem_u32(sm);
    const int tid  = threadIdx.x;
    const int wid  = tid >> 5;
    const int lane = tid & 31;
    const int mat  = blockIdx.y;
    const int row0 = blockIdx.x * 64;

    // fill A tiles (hi, lo): 64 rows x 16 uint4
    {
        const uint4* xh = reinterpret_cast<const uint4*>(g_xhi);
        const uint4* xl = reinterpret_cast<const uint4*>(g_xlo);
        for (int i = tid; i < 64 * 16; i += 256) {
            int r = i >> 4, c = i & 15;
            int gr = row0 + r;
            if (gr >= n) gr = n - 1;
            *reinterpret_cast<uint4*>(sm + OFF_AHI + r * PITCH + c * 16) = xh[gr * 16 + c];
            *reinterpret_cast<uint4*>(sm + OFF_ALO + r * PITCH + c * 16) = xl[gr * 16 + c];
        }
        // one matrix = 128*128 bf16 = 2048 uint4
        const uint4* wh = reinterpret_cast<const uint4*>(g_wthi) + mat * 2048;
        const uint4* wl = reinterpret_cast<const uint4*>(g_wtlo) + mat * 2048;
        for (int i = tid; i < 128 * 16; i += 256) {
            int r = i >> 4, c = i & 15;
            *reinterpret_cast<uint4*>(sm + OFF_BHI + r * PITCH + c * 16) = wh[r * 16 + c];
            *reinterpret_cast<uint4*>(sm + OFF_BLO + r * PITCH + c * 16) = wl[r * 16 + c];
        }
    }
    __syncthreads();

    const int mbase = (wid >> 2) * 32;
    const int nbase = (wid & 3) * 32;

    float acc[2][4][4];
#pragma unroll
    for (int mt = 0; mt < 2; mt++)
#pragma unroll
        for (int nt = 0; nt < 4; nt++)
#pragma unroll
            for (int q = 0; q < 4; q++) acc[mt][nt][q] = 0.f;

    const int arow  = lane & 15;
    const int akoff = (lane >> 4) << 4;
    const int brow  = lane & 7;
    const int bkoff = ((lane >> 3) & 1) << 4;

    for (int ks = 0; ks < 8; ++ks) {
        const int kb = ks * 32;
        uint32_t ah[2][4], al[2][4];
#pragma unroll
        for (int mt = 0; mt < 2; mt++) {
            uint32_t addr = sbase + OFF_AHI + (mbase + mt * 16 + arow) * PITCH + kb + akoff;
            ldm_x4(ah[mt], addr);
            ldm_x4(al[mt], addr + (OFF_ALO - OFF_AHI));
        }
        uint32_t bh[4][2], bo[4][2];
#pragma unroll
        for (int nt = 0; nt < 4; nt++) {
            uint32_t addr = sbase + OFF_BHI + (nbase + nt * 8 + brow) * PITCH + kb + bkoff;
            ldm_x2(bh[nt], addr);
            ldm_x2(bo[nt], addr + (OFF_BLO - OFF_BHI));
        }
#pragma unroll
        for (int mt = 0; mt < 2; mt++) {
#pragma unroll
            for (int nt = 0; nt < 4; nt++) {
                mma_bf16(acc[mt][nt], ah[mt], bh[nt]);
                mma_bf16(acc[mt][nt], ah[mt], bo[nt]);
                mma_bf16(acc[mt][nt], al[mt], bh[nt]);
            }
        }
    }

    const float* __restrict__ b = mat ? br : bl;
    float* __restrict__ C = mat ? g_gr1 : g_gl1;
    const int rql = lane >> 2;
    const int cql = (lane & 3) * 2;
#pragma unroll
    for (int mt = 0; mt < 2; mt++) {
        int r0 = row0 + mbase + mt * 16 + rql;
        int r1 = r0 + 8;
#pragma unroll
        for (int nt = 0; nt < 4; nt++) {
            int col = nbase + nt * 8 + cql;
            float2 bv = *reinterpret_cast<const float2*>(b + col);
            if (r0 < n) {
                float2 v = make_float2(acc[mt][nt][0] + bv.x, acc[mt][nt][1] + bv.y);
                *reinterpret_cast<float2*>(C + r0 * 128 + col) = v;
            }
            if (r1 < n) {
                float2 v = make_float2(acc[mt][nt][2] + bv.x, acc[mt][nt][3] + bv.y);
                *reinterpret_cast<float2*>(C + r1 * 128 + col) = v;
            }
        }
    }
}

// ---------------- layer-2 GEMM via mma.sync bf16-split (N=32) -----------------------
// grid (391, 2): 128 rows x 32 cols of mat = blockIdx.y. 256 threads (8 warps).
// Warp w handles rows w*16..w*16+15, all 32 cols.
__global__ __launch_bounds__(256) void gemm2_mma_kernel(
    int n, const float* __restrict__ bl, const float* __restrict__ br)
{
    constexpr int PITCH   = 272;
    constexpr int A_TILE  = 128 * PITCH;         // 34816
    constexpr int B_TILE  = 32 * PITCH;          // 8704
    constexpr int OFF_AHI = 0;
    constexpr int OFF_ALO = A_TILE;
    constexpr int OFF_BHI = 2 * A_TILE;
    constexpr int OFF_BLO = 2 * A_TILE + B_TILE;

    extern __shared__ char sm[];
    const uint32_t sbase = smem_u32(sm);
    const int tid  = threadIdx.x;
    const int wid  = tid >> 5;
    const int lane = tid & 31;
    const int mat  = blockIdx.y;
    const int row0 = blockIdx.x * 128;

    {
        const uint4* xh = reinterpret_cast<const uint4*>(g_h1hi);
        const uint4* xl = reinterpret_cast<const uint4*>(g_h1lo);
        for (int i = tid; i < 128 * 16; i += 256) {
            int r = i >> 4, c = i & 15;
            int gr = row0 + r;
            if (gr >= n) gr = n - 1;
            *reinterpret_cast<uint4*>(sm + OFF_AHI + r * PITCH + c * 16) = xh[gr * 16 + c];
            *reinterpret_cast<uint4*>(sm + OFF_ALO + r * PITCH + c * 16) = xl[gr * 16 + c];
        }
        // one matrix = 32*128 bf16 = 512 uint4
        const uint4* wh = reinterpret_cast<const uint4*>(g_wt2hi) + mat * 512;
        const uint4* wl = reinterpret_cast<const uint4*>(g_wt2lo) + mat * 512;
        for (int i = tid; i < 32 * 16; i += 256) {
            int r = i >> 4, c = i & 15;
            *reinterpret_cast<uint4*>(sm + OFF_BHI + r * PITCH + c * 16) = wh[r * 16 + c];
            *reinterpret_cast<uint4*>(sm + OFF_BLO + r * PITCH + c * 16) = wl[r * 16 + c];
        }
    }
    __syncthreads();

    float acc[4][4];
#pragma unroll
    for (int nt = 0; nt < 4; nt++)
#pragma unroll
        for (int q = 0; q < 4; q++) acc[nt][q] = 0.f;

    const int arow  = lane & 15;
    const int akoff = (lane >> 4) << 4;
    const int brow  = lane & 7;
    const int bkoff = ((lane >> 3) & 1) << 4;

    for (int ks = 0; ks < 8; ++ks) {
        const int kb = ks * 32;
        uint32_t ah[4], al[4];
        uint32_t addr = sbase + OFF_AHI + (wid * 16 + arow) * PITCH + kb + akoff;
        ldm_x4(ah, addr);
        ldm_x4(al, addr + (OFF_ALO - OFF_AHI));
        uint32_t bh[4][2], bo[4][2];
#pragma unroll
        for (int nt = 0; nt < 4; nt++) {
            uint32_t baddr = sbase + OFF_BHI + (nt * 8 + brow) * PITCH + kb + bkoff;
            ldm_x2(bh[nt], baddr);
            ldm_x2(bo[nt], baddr + (OFF_BLO - OFF_BHI));
        }
#pragma unroll
        for (int nt = 0; nt < 4; nt++) {
            mma_bf16(acc[nt], ah, bh[nt]);
            mma_bf16(acc[nt], ah, bo[nt]);
            mma_bf16(acc[nt], al, bh[nt]);
        }
    }

    const float* __restrict__ b = mat ? br : bl;
    float* __restrict__ C = mat ? g_gr2 : g_gl2;
    const int rql = lane >> 2;
    const int cql = (lane & 3) * 2;
    int r0 = row0 + wid * 16 + rql;
    int r1 = r0 + 8;
#pragma unroll
    for (int nt = 0; nt < 4; nt++) {
        int col = nt * 8 + cql;
        float2 bv = *reinterpret_cast<const float2*>(b + col);
        if (r0 < n) {
            float2 v = make_float2(acc[nt][0] + bv.x, acc[nt][1] + bv.y);
            *reinterpret_cast<float2*>(C + r0 * 32 + col) = v;
        }
        if (r1 < n) {
            float2 v = make_float2(acc[nt][2] + bv.x, acc[nt][3] + bv.y);
            *reinterpret_cast<float2*>(C + r1 * 32 + col) = v;
        }
    }
}

// ---------------- CSR build ----------------
__global__ void csr_hist_kernel(const int* __restrict__ ei) {
    int i = blockIdx.x * blockDim.x + threadIdx.x;
    if (i < EE) atomicAdd(&g_cnt[ei[EE + i]], 1u);
}
__global__ __launch_bounds__(1024) void csr_scan_kernel() {
    __shared__ unsigned s[1024];
    const int T = 1024;
    const int CH = (NN + T - 1) / T;
    int t = threadIdx.x;
    int base = t * CH;
    unsigned sum = 0;
    for (int i = 0; i < CH; i++) {
        int j = base + i;
        if (j < NN) sum += g_cnt[j];
    }
    s[t] = sum;
    __syncthreads();
    for (int off = 1; off < T; off <<= 1) {
        unsigned u = (t >= off) ? s[t - off] : 0u;
        __syncthreads();
        s[t] += u;
        __syncthreads();
    }
    unsigned run = s[t] - sum;
    for (int i = 0; i < CH; i++) {
        int j = base + i;
        if (j < NN) {
            unsigned c = g_cnt[j];
            g_cnt[j] = 0u;
            g_rowstart[j] = run;
            g_cursor[j]   = run;
            run += c;
        }
    }
    if (t == T - 1) g_rowstart[NN] = run;
}
__global__ void csr_fill_kernel(const int* __restrict__ ei) {
    int i = blockIdx.x * blockDim.x + threadIdx.x;
    if (i < EE) {
        int d = ei[EE + i];
        unsigned pos = atomicAdd(&g_cursor[d], 1u);
        g_csrc[pos] = ei[i];
    }
}

// ---------------- layer 1: fused attention aggregation (warp per dst, depth-2) -------
// Epilogue now emits h1 directly as bf16 hi/lo (consumed by gemm2_mma).
__global__ __launch_bounds__(256) void agg1_kernel(const float* __restrict__ att,
                                                   const float* __restrict__ bias) {
    const int lane = threadIdx.x & 31;
    const int d = blockIdx.x * (blockDim.x >> 5) + (threadIdx.x >> 5);
    if (d >= NN) return;

    const float4* __restrict__ gl4 = reinterpret_cast<const float4*>(g_gl1);
    const float4  grd = reinterpret_cast<const float4*>(g_gr1)[d * 32 + lane];
    const float4  at  = reinterpret_cast<const float4*>(att)[lane];

    float4 acc = make_float4(0.f, 0.f, 0.f, 0.f);
    float  den = 0.f;

    const unsigned start = g_rowstart[d];
    const unsigned deg   = g_rowstart[d + 1] - start;

    int s1 = (deg > 0) ? g_csrc[start]     : d;
    int s2 = (deg > 1) ? g_csrc[start + 1] : d;
    float4 gcur  = gl4[d  * 32 + lane];
    float4 gnext = gl4[s1 * 32 + lane];

    for (unsigned j = 0; j <= deg; ++j) {
        float4 gnn = gl4[s2 * 32 + lane];
        s2 = (j + 3 <= deg) ? g_csrc[start + j + 2] : d;

        float m0 = gcur.x + grd.x; m0 = (m0 > 0.f) ? m0 : NEG * m0;
        float m1 = gcur.y + grd.y; m1 = (m1 > 0.f) ? m1 : NEG * m1;
        float m2 = gcur.z + grd.z; m2 = (m2 > 0.f) ? m2 : NEG * m2;
        float m3 = gcur.w + grd.w; m3 = (m3 > 0.f) ? m3 : NEG * m3;
        float p = at.x * m0 + at.y * m1 + at.z * m2 + at.w * m3;
        p += __shfl_xor_sync(0xffffffffu, p, 1);
        p += __shfl_xor_sync(0xffffffffu, p, 2);
        p += __shfl_xor_sync(0xffffffffu, p, 4);
        float w = __expf(p);
        acc.x += w * gcur.x;
        acc.y += w * gcur.y;
        acc.z += w * gcur.z;
        acc.w += w * gcur.w;
        den += w;

        gcur = gnext;
        gnext = gnn;
    }

    const float inv = 1.f / den;
    const float4 b = reinterpret_cast<const float4*>(bias)[lane];
    float v0 = acc.x * inv + b.x; v0 = (v0 > 0.f) ? v0 : expm1f(v0);
    float v1 = acc.y * inv + b.y; v1 = (v1 > 0.f) ? v1 : expm1f(v1);
    float v2 = acc.z * inv + b.z; v2 = (v2 > 0.f) ? v2 : expm1f(v2);
    float v3 = acc.w * inv + b.w; v3 = (v3 > 0.f) ? v3 : expm1f(v3);

    float h0 = __bfloat162float(__float2bfloat16(v0));
    float h1 = __bfloat162float(__float2bfloat16(v1));
    float h2 = __bfloat162float(__float2bfloat16(v2));
    float h3 = __bfloat162float(__float2bfloat16(v3));
    uint2 hw, lw;
    hw.x = pack_bf2(v0, v1);
    hw.y = pack_bf2(v2, v3);
    lw.x = pack_bf2(v0 - h0, v1 - h1);
    lw.y = pack_bf2(v2 - h2, v3 - h3);
    reinterpret_cast<uint2*>(g_h1hi)[d * 32 + lane] = hw;
    reinterpret_cast<uint2*>(g_h1lo)[d * 32 + lane] = lw;
}

// ---------------- layer 2: aggregation, 4 dsts per warp (8 lanes / dst) -------------
__global__ __launch_bounds__(256) void agg2_kernel(const float* __restrict__ att,
                                                   const float* __restrict__ bias,
                                                   float* __restrict__ out) {
    const int lane = threadIdx.x & 31;
    const int grp  = lane >> 3;
    const int lg   = lane & 7;
    const int wid  = blockIdx.x * (blockDim.x >> 5) + (threadIdx.x >> 5);
    int d = wid * 4 + grp;
    const bool dvalid = (d < NN);
    if (d >= NN) d = NN - 1;

    const float4* __restrict__ gl4 = reinterpret_cast<const float4*>(g_gl2);
    const float4 grd  = reinterpret_cast<const float4*>(g_gr2)[d * 8 + lg];
    const float4 at   = reinterpret_cast<const float4*>(att)[lg];

    const unsigned start = g_rowstart[d];
    const unsigned deg   = dvalid ? (g_rowstart[d + 1] - start) : 0u;

    unsigned mdeg = deg;
#pragma unroll
    for (int off = 8; off < 32; off <<= 1) {
        unsigned o = __shfl_xor_sync(0xffffffffu, mdeg, off);
        mdeg = (o > mdeg) ? o : mdeg;
    }

    float4 acc = make_float4(0.f, 0.f, 0.f, 0.f);
    float  den = 0.f;

    int snext = (deg > 0) ? g_csrc[start] : d;
    float4 g = gl4[d * 8 + lg];

    for (unsigned j = 0; j <= mdeg; ++j) {
        float4 gc = g;
        int snn = (j + 2 <= deg) ? g_csrc[start + j + 1] : d;
        g = gl4[snext * 8 + lg];
        snext = snn;

        float m0 = gc.x + grd.x; m0 = (m0 > 0.f) ? m0 : NEG * m0;
        float m1 = gc.y + grd.y; m1 = (m1 > 0.f) ? m1 : NEG * m1;
        float m2 = gc.z + grd.z; m2 = (m2 > 0.f) ? m2 : NEG * m2;
        float m3 = gc.w + grd.w; m3 = (m3 > 0.f) ? m3 : NEG * m3;
        float p = at.x * m0 + at.y * m1 + at.z * m2 + at.w * m3;
        p += __shfl_xor_sync(0xffffffffu, p, 1);
        p += __shfl_xor_sync(0xffffffffu, p, 2);
        p += __shfl_xor_sync(0xffffffffu, p, 4);
        float w = (j <= deg) ? __expf(p) : 0.f;
        acc.x += w * gc.x;
        acc.y += w * gc.y;
        acc.z += w * gc.z;
        acc.w += w * gc.w;
        den += w;
    }

    if (dvalid) {
        const float inv = 1.f / den;
        const float4 b = reinterpret_cast<const float4*>(bias)[lg];
        reinterpret_cast<float4*>(out)[d * 8 + lg] =
            make_float4(acc.x * inv + b.x, acc.y * inv + b.y,
                        acc.z * inv + b.z, acc.w * inv + b.w);
    }
}

// ---------------- launch ----------------
extern "C" void kernel_launch(void* const* d_in, const int* in_sizes, int n_in,
                              void* d_out, int out_size) {
    const float* x    = (const float*)d_in[0];
    const int*   ei   = (const int*)d_in[1];
    const float* Wl1  = (const float*)d_in[2];
    const float* bl1  = (const float*)d_in[3];
    const float* Wr1  = (const float*)d_in[4];
    const float* br1  = (const float*)d_in[5];
    const float* att1 = (const float*)d_in[6];
    const float* bias1= (const float*)d_in[7];
    const float* Wl2  = (const float*)d_in[8];
    const float* bl2  = (const float*)d_in[9];
    const float* Wr2  = (const float*)d_in[10];
    const float* br2  = (const float*)d_in[11];
    const float* att2 = (const float*)d_in[12];
    const float* bias2= (const float*)d_in[13];
    float* out = (float*)d_out;

    const int smem1 = 2 * (64 * 272) + 2 * (128 * 272);   // 104448 -> 2 blocks/SM
    const int smem2 = 2 * (128 * 272) + 2 * (32 * 272);   // 87040  -> 2 blocks/SM
    cudaFuncSetAttribute(gemm1_mma_kernel,
                         cudaFuncAttributeMaxDynamicSharedMemorySize, smem1);
    cudaFuncSetAttribute(gemm2_mma_kernel,
                         cudaFuncAttributeMaxDynamicSharedMemorySize, smem2);

    // slots 1-3: converts + hist; slot 4: gemm1_mma (PROFILED — expect occ ~25%)
    convert_x_kernel<<<(NN * 32 + 255) / 256, 256>>>(x);
    convert_w_kernel<<<(2 * 128 * 128 + 2 * 32 * 128 + 255) / 256, 256>>>(
        Wl1, Wr1, Wl2, Wr2);
    csr_hist_kernel<<<(EE + 255) / 256, 256>>>(ei);
    gemm1_mma_kernel<<<dim3((NN + 63) / 64, 2), 256, smem1>>>(NN, bl1, br1);
    csr_scan_kernel<<<1, 1024>>>();
    csr_fill_kernel<<<(EE + 255) / 256, 256>>>(ei);

    agg1_kernel<<<(NN + 7) / 8, 256>>>(att1, bias1);

    gemm2_mma_kernel<<<dim3((NN + 127) / 128, 2), 256, smem2>>>(NN, bl2, br2);
    agg2_kernel<<<(NN + 31) / 32, 256>>>(att2, bias2, out);
}